// round 1
// baseline (speedup 1.0000x reference)
#include <cuda_runtime.h>
#include <cstdint>
#include <cmath>

// ---------------------------------------------------------------------------
// Problem constants: B=8, L=2048, D=1024 (H=16, E=64 -> C = H*E = 1024), topk=22
// ---------------------------------------------------------------------------
#define BATCH 8
#define SEQ   2048
#define DIM   1024
#define TOPK  22
#define ELEMS (BATCH * SEQ * DIM)   // 16777216

// Scratch (allocation-free: __device__ globals)
__device__ float g_Qb[ELEMS];     // Q = queries@Wq+bq, [B,L,C]
__device__ float g_Kb[ELEMS];     // K
__device__ float g_Qt[ELEMS];     // Q transposed [B,C,L]
__device__ float g_Kt[ELEMS];     // K transposed [B,C,L]
__device__ float g_corr[ELEMS];   // corr [B,C,L]
__device__ float g_Vs[BATCH * 8 * DIM];  // V rows l=0..7 only
__device__ float g_Rs[BATCH * 8 * DIM];  // aggregated result (periodic rows)
__device__ float g_To[BATCH * 8 * DIM];  // Rs @ Wo + bo

// ---------------------------------------------------------------------------
// GEMM: Y[M,1024] = X[M,1024] @ W[1024,1024] + bias   (fp32 SIMT, 128x128x16)
// ---------------------------------------------------------------------------
__global__ __launch_bounds__(256) void sgemm_bias(
    const float* __restrict__ X, const float* __restrict__ W,
    const float* __restrict__ bias, float* __restrict__ Y)
{
    const int n0 = blockIdx.x * 128;
    const int m0 = blockIdx.y * 128;
    const int tid = threadIdx.x;
    const int tx = tid & 15, ty = tid >> 4;

    __shared__ float As[16][132];  // [k][m]
    __shared__ float Bs[16][132];  // [k][n]

    float acc[8][8];
#pragma unroll
    for (int i = 0; i < 8; i++)
#pragma unroll
        for (int j = 0; j < 8; j++) acc[i][j] = 0.0f;

    for (int k0 = 0; k0 < 1024; k0 += 16) {
#pragma unroll
        for (int t = 0; t < 2; t++) {
            int id = tid + t * 256;
            int arow = id >> 2, ac4 = id & 3;
            float4 av = *(const float4*)(X + (size_t)(m0 + arow) * 1024 + k0 + ac4 * 4);
            As[ac4 * 4 + 0][arow] = av.x;
            As[ac4 * 4 + 1][arow] = av.y;
            As[ac4 * 4 + 2][arow] = av.z;
            As[ac4 * 4 + 3][arow] = av.w;
            int brow = id >> 5, bc4 = id & 31;
            float4 bv = *(const float4*)(W + (size_t)(k0 + brow) * 1024 + n0 + bc4 * 4);
            *(float4*)(&Bs[brow][bc4 * 4]) = bv;
        }
        __syncthreads();
#pragma unroll
        for (int kk = 0; kk < 16; kk++) {
            float ar[8], br[8];
#pragma unroll
            for (int i = 0; i < 8; i++) ar[i] = As[kk][ty * 8 + i];
#pragma unroll
            for (int j = 0; j < 8; j++) br[j] = Bs[kk][tx * 8 + j];
#pragma unroll
            for (int i = 0; i < 8; i++)
#pragma unroll
                for (int j = 0; j < 8; j++) acc[i][j] += ar[i] * br[j];
        }
        __syncthreads();
    }
#pragma unroll
    for (int i = 0; i < 8; i++) {
        int m = m0 + ty * 8 + i;
#pragma unroll
        for (int j = 0; j < 8; j++) {
            int n = n0 + tx * 8 + j;
            Y[(size_t)m * 1024 + n] = acc[i][j] + bias[n];
        }
    }
}

// ---------------------------------------------------------------------------
// Small GEMM: 64 rows.  Y[r,:] = Xrow(r) @ W + bias.
// Row r maps to X + (r/8)*b_stride + (r%8)*1024.
// ---------------------------------------------------------------------------
__global__ __launch_bounds__(256) void rowgemm64(
    const float* __restrict__ X, const float* __restrict__ W,
    const float* __restrict__ bias, float* __restrict__ Y, size_t b_stride)
{
    const int r = blockIdx.x;
    const float* xrow = X + (size_t)(r >> 3) * b_stride + (size_t)(r & 7) * 1024;
    __shared__ float xs[1024];
    const int tid = threadIdx.x;
    for (int i = tid; i < 1024; i += 256) xs[i] = xrow[i];
    __syncthreads();
    float a0 = 0.f, a1 = 0.f, a2 = 0.f, a3 = 0.f;
#pragma unroll 4
    for (int k = 0; k < 1024; k++) {
        float xv = xs[k];
        const float* wr = W + (size_t)k * 1024;
        a0 += xv * wr[tid];
        a1 += xv * wr[tid + 256];
        a2 += xv * wr[tid + 512];
        a3 += xv * wr[tid + 768];
    }
    float* yr = Y + (size_t)r * 1024;
    yr[tid]       = a0 + bias[tid];
    yr[tid + 256] = a1 + bias[tid + 256];
    yr[tid + 512] = a2 + bias[tid + 512];
    yr[tid + 768] = a3 + bias[tid + 768];
}

// ---------------------------------------------------------------------------
// Batched 2D transpose: out[b, j, i] = in[b, i, j], i<R, j<C (R,C mult of 32)
// ---------------------------------------------------------------------------
__global__ void transpose_bRC(const float* __restrict__ in, float* __restrict__ out,
                              int R, int C)
{
    __shared__ float tile[32][33];
    const int bz = blockIdx.z;
    const float* ip = in + (size_t)bz * R * C;
    float* op = out + (size_t)bz * R * C;
    const int j0 = blockIdx.x * 32;
    const int i0 = blockIdx.y * 32;
    const int tx = threadIdx.x, ty = threadIdx.y;
#pragma unroll
    for (int k = 0; k < 4; k++)
        tile[ty + k * 8][tx] = ip[(size_t)(i0 + ty + k * 8) * C + (j0 + tx)];
    __syncthreads();
#pragma unroll
    for (int k = 0; k < 4; k++)
        op[(size_t)(j0 + ty + k * 8) * R + (i0 + tx)] = tile[tx][ty + k * 8];
}

// ---------------------------------------------------------------------------
// In-shared-memory Stockham radix-2 FFT, N=2048, 256 threads.
// Forward: sign=-1.  Inverse (unnormalized): sign=+1.
// Ping-pongs A<->B each stage; with 11 stages the result lands in B.
// ---------------------------------------------------------------------------
__device__ __forceinline__ void fft2048_stages(float2* __restrict__ A,
                                               float2* __restrict__ B,
                                               int tid, float sign)
{
    float2* x = A;
    float2* y = B;
#pragma unroll
    for (int st = 0; st < 11; st++) {
        const int ls = st;               // log2(s)
        const int nlog = 11 - st;        // current sub-transform log size
        const float cst = sign * 6.28318530717958647692f / (float)(1 << nlog);
#pragma unroll
        for (int u = 0; u < 4; u++) {
            const int idx = tid + (u << 8);       // 0..1023
            const int p = idx >> ls;
            float2 a  = x[idx];
            float2 b2 = x[idx + 1024];
            float si, co;
            sincosf(cst * (float)p, &si, &co);
            float2 s = make_float2(a.x + b2.x, a.y + b2.y);
            float2 d = make_float2(a.x - b2.x, a.y - b2.y);
            float2 t = make_float2(d.x * co - d.y * si, d.x * si + d.y * co);
            const int w0 = idx + (p << ls);
            y[w0] = s;
            y[w0 + (1 << ls)] = t;
        }
        __syncthreads();
        float2* tmp = x; x = y; y = tmp;
    }
}

// ---------------------------------------------------------------------------
// Per-(b,c) kernel: packed FFT correlation -> corr, then top-22 + softmax +
// mod-8 V aggregation (agg is periodic in l with period 8).
// ---------------------------------------------------------------------------
__global__ __launch_bounds__(256) void fft_corr_topk(
    const float* __restrict__ Qt, const float* __restrict__ Kt,
    const float* __restrict__ Vs, float* __restrict__ corrS,
    float* __restrict__ Rsmall)
{
    __shared__ float2 SA[2048];
    __shared__ float2 SB[2048];
    __shared__ float topv[TOPK];
    __shared__ int   topd[TOPK];
    __shared__ float wts[TOPK];
    __shared__ float vsh[8];

    const int tid = threadIdx.x;
    const int bidx = blockIdx.x;              // b*1024 + c
    const int b = bidx >> 10;
    const int c = bidx & 1023;

    const float* qp = Qt + (size_t)bidx * 2048;
    const float* kp = Kt + (size_t)bidx * 2048;
    for (int l = tid; l < 2048; l += 256) SA[l] = make_float2(qp[l], kp[l]);
    __syncthreads();

    // Forward FFT of z = q + i*k  -> Z in SB
    fft2048_stages(SA, SB, tid, -1.0f);

    // P[f] = Q[f]*conj(K[f]) = 0.25i * (a + conj(b)) * (conj(a) - b)
    for (int f = tid; f < 2048; f += 256) {
        float2 a  = SB[f];
        float2 bz = SB[(2048 - f) & 2047];
        float ux = a.x + bz.x, uy = a.y - bz.y;
        float vx = a.x - bz.x, vy = -a.y - bz.y;
        float pr = ux * vx - uy * vy;
        float pi = ux * vy + uy * vx;
        SA[f] = make_float2(-0.25f * pi, 0.25f * pr);
    }
    __syncthreads();

    // Inverse FFT of P -> SB (real part * 1/N is corr)
    fft2048_stages(SA, SB, tid, +1.0f);

    float* corrf = (float*)SA;  // SA free now; reuse as float array
    const float invN = 1.0f / 2048.0f;
    float* cg = corrS + (size_t)bidx * 2048;
    for (int n = tid; n < 2048; n += 256) {
        float v = SB[n].x * invN;
        corrf[n] = v;
        cg[n] = v;
    }
    __syncthreads();

    // ---- top-22 (warp 0), tie-break = lowest index (matches lax.top_k) ----
    if (tid < 32) {
        const int lane = tid;
        for (int r = 0; r < TOPK; r++) {
            float best = -1e30f; int bi = 0x7fffffff;
#pragma unroll 8
            for (int j = 0; j < 64; j++) {
                float v = corrf[(j << 5) + lane];
                if (v > best) { best = v; bi = (j << 5) + lane; }
            }
#pragma unroll
            for (int off = 16; off > 0; off >>= 1) {
                float ov = __shfl_down_sync(0xffffffffu, best, off);
                int   oi = __shfl_down_sync(0xffffffffu, bi, off);
                if (ov > best || (ov == best && oi < bi)) { best = ov; bi = oi; }
            }
            best = __shfl_sync(0xffffffffu, best, 0);
            bi   = __shfl_sync(0xffffffffu, bi, 0);
            if (lane == 0) { topv[r] = best; topd[r] = bi; }
            if ((bi & 31) == lane) corrf[bi] = -1e30f;
            __syncwarp();
        }
        // softmax over the 22 (descending) values
        float e = 0.0f;
        const float mx = topv[0];
        if (lane < TOPK) { e = expf(topv[lane] - mx); wts[lane] = e; }
        float ssum = e;
#pragma unroll
        for (int off = 16; off > 0; off >>= 1)
            ssum += __shfl_down_sync(0xffffffffu, ssum, off);
        ssum = __shfl_sync(0xffffffffu, ssum, 0);
        const float inv = 1.0f / ssum;
        if (lane < 8) vsh[lane] = Vs[(size_t)(((b << 3) + lane) << 10) + c];
        __syncwarp();
        if (lane < 8) {
            float acc = 0.0f;
#pragma unroll
            for (int i = 0; i < TOPK; i++)
                acc += wts[i] * vsh[(lane + topd[i]) & 7];
            Rsmall[(size_t)(((b << 3) + lane) << 10) + c] = acc * inv;
        }
    }
}

// ---------------------------------------------------------------------------
// Broadcast: out[b,l,:] = Tout[b*8 + (l%8), :]
// ---------------------------------------------------------------------------
__global__ void broadcast_out(const float* __restrict__ Tout, float* __restrict__ out)
{
    const size_t idx = (size_t)blockIdx.x * 256 + threadIdx.x;  // < ELEMS
    const int cc = (int)(idx & 1023);
    const int l  = (int)((idx >> 10) & 2047);
    const int bb = (int)(idx >> 21);
    out[idx] = Tout[(size_t)(((bb << 3) + (l & 7)) << 10) + cc];
}

// ---------------------------------------------------------------------------
extern "C" void kernel_launch(void* const* d_in, const int* in_sizes, int n_in,
                              void* d_out, int out_size)
{
    const float* queries = (const float*)d_in[0];
    const float* keys    = (const float*)d_in[1];
    const float* values  = (const float*)d_in[2];
    const float* Wq = (const float*)d_in[3];
    const float* bq = (const float*)d_in[4];
    const float* Wk = (const float*)d_in[5];
    const float* bk = (const float*)d_in[6];
    const float* Wv = (const float*)d_in[7];
    const float* bv = (const float*)d_in[8];
    const float* Wo = (const float*)d_in[9];
    const float* bo = (const float*)d_in[10];
    float* out = (float*)d_out;

    float *Qb, *Kb, *Qt, *Kt, *corrS, *Vs, *Rs, *To;
    cudaGetSymbolAddress((void**)&Qb, g_Qb);
    cudaGetSymbolAddress((void**)&Kb, g_Kb);
    cudaGetSymbolAddress((void**)&Qt, g_Qt);
    cudaGetSymbolAddress((void**)&Kt, g_Kt);
    cudaGetSymbolAddress((void**)&corrS, g_corr);
    cudaGetSymbolAddress((void**)&Vs, g_Vs);
    cudaGetSymbolAddress((void**)&Rs, g_Rs);
    cudaGetSymbolAddress((void**)&To, g_To);

    dim3 gemmGrid(1024 / 128, (BATCH * SEQ) / 128);  // (8, 128)

    // Projections (V only needs rows l = 0..7 per batch!)
    sgemm_bias<<<gemmGrid, 256>>>(queries, Wq, bq, Qb);
    sgemm_bias<<<gemmGrid, 256>>>(keys, Wk, bk, Kb);
    rowgemm64<<<64, 256>>>(values, Wv, bv, Vs, (size_t)SEQ * DIM);

    // [B,L,C] -> [B,C,L]
    transpose_bRC<<<dim3(1024 / 32, 2048 / 32, BATCH), dim3(32, 8)>>>(Qb, Qt, 2048, 1024);
    transpose_bRC<<<dim3(1024 / 32, 2048 / 32, BATCH), dim3(32, 8)>>>(Kb, Kt, 2048, 1024);

    // FFT correlation + top-k + mod-8 aggregation
    fft_corr_topk<<<BATCH * DIM, 256>>>(Qt, Kt, Vs, corrS, Rs);

    // corr [B,C,L] -> second output half [B,L,C]
    transpose_bRC<<<dim3(2048 / 32, 1024 / 32, BATCH), dim3(32, 8)>>>(corrS, out + (size_t)ELEMS, 1024, 2048);

    // out = result @ Wo + bo  (result rows are periodic: only 64 distinct rows)
    rowgemm64<<<64, 256>>>(Rs, Wo, bo, To, (size_t)8 * DIM);
    broadcast_out<<<ELEMS / 256, 256>>>(To, out);
}

// round 3
// speedup vs baseline: 1.3838x; 1.3838x over previous
#include <cuda_runtime.h>
#include <cuda_bf16.h>
#include <cstdint>
#include <cmath>

// ---------------------------------------------------------------------------
// Problem constants: B=8, L=2048, D=1024 (H=16, E=64 -> C = 1024), topk=22
// ---------------------------------------------------------------------------
#define BATCH 8
#define SEQ   2048
#define DIM   1024
#define TOPK  22
#define ELEMS (BATCH * SEQ * DIM)   // 16777216

// Scratch (allocation-free: __device__ globals)
__device__ float g_Qb[ELEMS];     // Q = queries@Wq+bq, [B,L,C]
__device__ float g_Kb[ELEMS];     // K
__device__ float g_Qt[ELEMS];     // Q transposed [B,C,L]
__device__ float g_Kt[ELEMS];     // K transposed [B,C,L]
__device__ float g_corr[ELEMS];   // corr [B,C,L]
__device__ float g_Vs[BATCH * 8 * DIM];  // V rows l=0..7 only
__device__ float g_Rs[BATCH * 8 * DIM];  // aggregated result (periodic rows)
__device__ float g_To[BATCH * 8 * DIM];  // Rs @ Wo + bo
__device__ __nv_bfloat16 g_Xhi[ELEMS];   // split-bf16 staging for activations
__device__ __nv_bfloat16 g_Xlo[ELEMS];
__device__ __nv_bfloat16 g_Whi[DIM * DIM];
__device__ __nv_bfloat16 g_Wlo[DIM * DIM];
__device__ float2 g_tw[1024];            // FFT twiddles exp(+i 2 pi p / 2048)

// ---------------------------------------------------------------------------
// Split fp32 -> (hi, lo) bf16 pair.  x ~= hi + lo with ~17-bit mantissa.
// ---------------------------------------------------------------------------
__global__ void split_bf16(const float* __restrict__ x,
                           __nv_bfloat16* __restrict__ hi,
                           __nv_bfloat16* __restrict__ lo)
{
    const int i = blockIdx.x * 256 + threadIdx.x;  // one float4 per thread
    float4 v = ((const float4*)x)[i];
    float vv[4] = {v.x, v.y, v.z, v.w};
    __nv_bfloat16 h[4], l[4];
#pragma unroll
    for (int j = 0; j < 4; j++) {
        h[j] = __float2bfloat16(vv[j]);
        l[j] = __float2bfloat16(vv[j] - __bfloat162float(h[j]));
    }
    *(uint2*)(hi + 4 * (size_t)i) = *(uint2*)h;
    *(uint2*)(lo + 4 * (size_t)i) = *(uint2*)l;
}

// ---------------------------------------------------------------------------
// Tensor-core GEMM:  Y[M,1024] = X @ W + bias  (fp32-ish via 3x bf16 mma)
// Block tile 128x128, k-step 16, cp.async double buffering, 8 warps (2x4).
// ---------------------------------------------------------------------------
#define APAD 24    // A smem row length in halves (16 data + 8 pad) -> 48B rows
#define BPAD 136   // B smem row length in halves (128 data + 8 pad) -> 272B rows

__device__ __forceinline__ void cp16(uint32_t d, const void* s) {
    asm volatile("cp.async.cg.shared.global [%0], [%1], 16;\n" :: "r"(d), "l"(s));
}
__device__ __forceinline__ void cp_commit() { asm volatile("cp.async.commit_group;\n"); }
__device__ __forceinline__ void cp_wait0()  { asm volatile("cp.async.wait_group 0;\n"); }

__device__ __forceinline__ void ldsm4(uint32_t* r, uint32_t a) {
    asm volatile("ldmatrix.sync.aligned.m8n8.x4.shared.b16 {%0,%1,%2,%3},[%4];"
                 : "=r"(r[0]), "=r"(r[1]), "=r"(r[2]), "=r"(r[3]) : "r"(a));
}
__device__ __forceinline__ void ldsm4t(uint32_t* r, uint32_t a) {
    asm volatile("ldmatrix.sync.aligned.m8n8.x4.trans.shared.b16 {%0,%1,%2,%3},[%4];"
                 : "=r"(r[0]), "=r"(r[1]), "=r"(r[2]), "=r"(r[3]) : "r"(a));
}
__device__ __forceinline__ void mma_bf16(float* c, const uint32_t* a, const uint32_t* b) {
    asm volatile("mma.sync.aligned.m16n8k16.row.col.f32.bf16.bf16.f32 "
                 "{%0,%1,%2,%3},{%4,%5,%6,%7},{%8,%9},{%0,%1,%2,%3};"
                 : "+f"(c[0]), "+f"(c[1]), "+f"(c[2]), "+f"(c[3])
                 : "r"(a[0]), "r"(a[1]), "r"(a[2]), "r"(a[3]), "r"(b[0]), "r"(b[1]));
}

__global__ __launch_bounds__(256) void gemm_bf16x2(
    const __nv_bfloat16* __restrict__ Ahi, const __nv_bfloat16* __restrict__ Alo,
    const __nv_bfloat16* __restrict__ Bhi, const __nv_bfloat16* __restrict__ Blo,
    const float* __restrict__ bias, float* __restrict__ Y)
{
    __shared__ __nv_bfloat16 sAh[2][128 * APAD];
    __shared__ __nv_bfloat16 sAl[2][128 * APAD];
    __shared__ __nv_bfloat16 sBh[2][16 * BPAD];
    __shared__ __nv_bfloat16 sBl[2][16 * BPAD];

    const int tid = threadIdx.x;
    const int warp = tid >> 5, lane = tid & 31;
    const int wm = warp >> 2, wn = warp & 3;          // 2 x 4 warp grid
    const int m0 = blockIdx.y * 128, n0 = blockIdx.x * 128;

    float acc[4][4][4];
#pragma unroll
    for (int i = 0; i < 4; i++)
#pragma unroll
        for (int j = 0; j < 4; j++)
#pragma unroll
            for (int k = 0; k < 4; k++) acc[i][j][k] = 0.0f;

    const int a_m = tid >> 1, a_c = tid & 1;   // A: 128 rows x 2 16B chunks
    const int b_k = tid >> 4, b_c = tid & 15;  // B: 16 rows x 16 16B chunks

#define GEMM_ISSUE(buf, k0)                                                          \
    do {                                                                             \
        cp16((uint32_t)__cvta_generic_to_shared(&sAh[buf][a_m * APAD + a_c * 8]),    \
             Ahi + (size_t)(m0 + a_m) * 1024 + (k0) + a_c * 8);                      \
        cp16((uint32_t)__cvta_generic_to_shared(&sAl[buf][a_m * APAD + a_c * 8]),    \
             Alo + (size_t)(m0 + a_m) * 1024 + (k0) + a_c * 8);                      \
        cp16((uint32_t)__cvta_generic_to_shared(&sBh[buf][b_k * BPAD + b_c * 8]),    \
             Bhi + (size_t)((k0) + b_k) * 1024 + n0 + b_c * 8);                      \
        cp16((uint32_t)__cvta_generic_to_shared(&sBl[buf][b_k * BPAD + b_c * 8]),    \
             Blo + (size_t)((k0) + b_k) * 1024 + n0 + b_c * 8);                      \
        cp_commit();                                                                 \
    } while (0)

    GEMM_ISSUE(0, 0);

    const int ar = lane & 15, ac8 = (lane >> 4) * 8;    // ldmatrix lane addressing

    for (int it = 0; it < 64; it++) {
        cp_wait0();
        __syncthreads();
        if (it + 1 < 64) GEMM_ISSUE((it + 1) & 1, (it + 1) * 16);

        const int buf = it & 1;
        uint32_t ah[4][4], al[4][4], bh[4][2], bl[4][2];
#pragma unroll
        for (int mb = 0; mb < 4; mb++) {
            const int row = wm * 64 + mb * 16 + ar;
            ldsm4(ah[mb], (uint32_t)__cvta_generic_to_shared(&sAh[buf][row * APAD + ac8]));
            ldsm4(al[mb], (uint32_t)__cvta_generic_to_shared(&sAl[buf][row * APAD + ac8]));
        }
#pragma unroll
        for (int nb2 = 0; nb2 < 2; nb2++) {
            uint32_t r[4];
            const int col = wn * 32 + nb2 * 16 + ac8;
            ldsm4t(r, (uint32_t)__cvta_generic_to_shared(&sBh[buf][ar * BPAD + col]));
            bh[nb2 * 2][0] = r[0]; bh[nb2 * 2][1] = r[1];
            bh[nb2 * 2 + 1][0] = r[2]; bh[nb2 * 2 + 1][1] = r[3];
            ldsm4t(r, (uint32_t)__cvta_generic_to_shared(&sBl[buf][ar * BPAD + col]));
            bl[nb2 * 2][0] = r[0]; bl[nb2 * 2][1] = r[1];
            bl[nb2 * 2 + 1][0] = r[2]; bl[nb2 * 2 + 1][1] = r[3];
        }
#pragma unroll
        for (int mb = 0; mb < 4; mb++)
#pragma unroll
            for (int nb = 0; nb < 4; nb++) {
                mma_bf16(acc[mb][nb], ah[mb], bh[nb]);   // hi*hi
                mma_bf16(acc[mb][nb], ah[mb], bl[nb]);   // hi*lo
                mma_bf16(acc[mb][nb], al[mb], bh[nb]);   // lo*hi
            }
        __syncthreads();
    }

    // Epilogue: fragment -> global with bias
    const int g = lane >> 2, t2 = (lane & 3) * 2;
#pragma unroll
    for (int mb = 0; mb < 4; mb++) {
        const int row0 = m0 + wm * 64 + mb * 16 + g;
#pragma unroll
        for (int nb = 0; nb < 4; nb++) {
            const int col = n0 + wn * 32 + nb * 8 + t2;
            const float b0 = bias[col], b1 = bias[col + 1];
            float2 v0 = make_float2(acc[mb][nb][0] + b0, acc[mb][nb][1] + b1);
            float2 v1 = make_float2(acc[mb][nb][2] + b0, acc[mb][nb][3] + b1);
            *(float2*)&Y[(size_t)row0 * 1024 + col] = v0;
            *(float2*)&Y[(size_t)(row0 + 8) * 1024 + col] = v1;
        }
    }
}

// ---------------------------------------------------------------------------
// Small GEMM: 64 rows.  Y[r,:] = Xrow(r) @ W + bias.
// Row r maps to X + (r/8)*b_stride + (r%8)*1024.
// ---------------------------------------------------------------------------
__global__ __launch_bounds__(256) void rowgemm64(
    const float* __restrict__ X, const float* __restrict__ W,
    const float* __restrict__ bias, float* __restrict__ Y, size_t b_stride)
{
    const int r = blockIdx.x;
    const float* xrow = X + (size_t)(r >> 3) * b_stride + (size_t)(r & 7) * 1024;
    __shared__ float xs[1024];
    const int tid = threadIdx.x;
    for (int i = tid; i < 1024; i += 256) xs[i] = xrow[i];
    __syncthreads();
    float a0 = 0.f, a1 = 0.f, a2 = 0.f, a3 = 0.f;
#pragma unroll 4
    for (int k = 0; k < 1024; k++) {
        float xv = xs[k];
        const float* wr = W + (size_t)k * 1024;
        a0 += xv * wr[tid];
        a1 += xv * wr[tid + 256];
        a2 += xv * wr[tid + 512];
        a3 += xv * wr[tid + 768];
    }
    float* yr = Y + (size_t)r * 1024;
    yr[tid]       = a0 + bias[tid];
    yr[tid + 256] = a1 + bias[tid + 256];
    yr[tid + 512] = a2 + bias[tid + 512];
    yr[tid + 768] = a3 + bias[tid + 768];
}

// ---------------------------------------------------------------------------
// Batched 2D transpose: out[b, j, i] = in[b, i, j], i<R, j<C (R,C mult of 32)
// ---------------------------------------------------------------------------
__global__ void transpose_bRC(const float* __restrict__ in, float* __restrict__ out,
                              int R, int C)
{
    __shared__ float tile[32][33];
    const int bz = blockIdx.z;
    const float* ip = in + (size_t)bz * R * C;
    float* op = out + (size_t)bz * R * C;
    const int j0 = blockIdx.x * 32;
    const int i0 = blockIdx.y * 32;
    const int tx = threadIdx.x, ty = threadIdx.y;
#pragma unroll
    for (int k = 0; k < 4; k++)
        tile[ty + k * 8][tx] = ip[(size_t)(i0 + ty + k * 8) * C + (j0 + tx)];
    __syncthreads();
#pragma unroll
    for (int k = 0; k < 4; k++)
        op[(size_t)(j0 + ty + k * 8) * R + (i0 + tx)] = tile[tx][ty + k * 8];
}

// ---------------------------------------------------------------------------
// FFT twiddle table: g_tw[p] = (cos, sin)(2 pi p / 2048), p < 1024
// ---------------------------------------------------------------------------
__global__ void fill_tw(float2* tw)
{
    const int i = blockIdx.x * 256 + threadIdx.x;
    if (i < 1024) {
        float s, c;
        sincosf(6.28318530717958647692f * (float)i / 2048.0f, &s, &c);
        tw[i] = make_float2(c, s);
    }
}

// ---------------------------------------------------------------------------
// In-shared-memory Stockham radix-2 FFT, N=2048, 256 threads, table twiddles.
// Forward: sign=-1.  Inverse (unnormalized): sign=+1.
// ---------------------------------------------------------------------------
__device__ __forceinline__ void fft2048_stages(float2* __restrict__ A,
                                               float2* __restrict__ B,
                                               const float2* __restrict__ tws,
                                               int tid, float sign)
{
    float2* x = A;
    float2* y = B;
#pragma unroll
    for (int st = 0; st < 11; st++) {
        const int ls = st;
#pragma unroll
        for (int u = 0; u < 4; u++) {
            const int idx = tid + (u << 8);       // 0..1023
            const int p = idx >> ls;
            float2 a  = x[idx];
            float2 b2 = x[idx + 1024];
            float2 w  = tws[(p << ls) & 1023];    // theta = 2 pi p / 2^(11-st)
            const float co = w.x, si = sign * w.y;
            float2 s = make_float2(a.x + b2.x, a.y + b2.y);
            float2 d = make_float2(a.x - b2.x, a.y - b2.y);
            float2 t = make_float2(d.x * co - d.y * si, d.x * si + d.y * co);
            const int w0 = idx + (p << ls);
            y[w0] = s;
            y[w0 + (1 << ls)] = t;
        }
        __syncthreads();
        float2* tmp = x; x = y; y = tmp;
    }
}

// ---------------------------------------------------------------------------
// Per-(b,c) kernel: packed FFT correlation -> corr, then top-22 + softmax +
// mod-8 V aggregation (agg is periodic in l with period 8).
// ---------------------------------------------------------------------------
__global__ __launch_bounds__(256) void fft_corr_topk(
    const float* __restrict__ Qt, const float* __restrict__ Kt,
    const float* __restrict__ Vs, const float2* __restrict__ twg,
    float* __restrict__ corrS, float* __restrict__ Rsmall)
{
    __shared__ float2 SA[2048];
    __shared__ float2 SB[2048];
    __shared__ float2 tws[1024];
    __shared__ float topv[TOPK];
    __shared__ int   topd[TOPK];
    __shared__ float wts[TOPK];
    __shared__ float vsh[8];

    const int tid = threadIdx.x;
    const int bidx = blockIdx.x;              // b*1024 + c
    const int b = bidx >> 10;
    const int c = bidx & 1023;

    const float* qp = Qt + (size_t)bidx * 2048;
    const float* kp = Kt + (size_t)bidx * 2048;
    for (int l = tid; l < 2048; l += 256) SA[l] = make_float2(qp[l], kp[l]);
    for (int i = tid; i < 1024; i += 256) tws[i] = twg[i];
    __syncthreads();

    // Forward FFT of z = q + i*k  -> Z in SB
    fft2048_stages(SA, SB, tws, tid, -1.0f);

    // P[f] = Q[f]*conj(K[f]) = 0.25i * (a + conj(b)) * (conj(a) - b)
    for (int f = tid; f < 2048; f += 256) {
        float2 a  = SB[f];
        float2 bz = SB[(2048 - f) & 2047];
        float ux = a.x + bz.x, uy = a.y - bz.y;
        float vx = a.x - bz.x, vy = -a.y - bz.y;
        float pr = ux * vx - uy * vy;
        float pi = ux * vy + uy * vx;
        SA[f] = make_float2(-0.25f * pi, 0.25f * pr);
    }
    __syncthreads();

    // Inverse FFT of P -> SB (real part * 1/N is corr)
    fft2048_stages(SA, SB, tws, tid, +1.0f);

    float* corrf = (float*)SA;  // SA free now; reuse as float array
    const float invN = 1.0f / 2048.0f;
    float* cg = corrS + (size_t)bidx * 2048;
    for (int n = tid; n < 2048; n += 256) {
        float v = SB[n].x * invN;
        corrf[n] = v;
        cg[n] = v;
    }
    __syncthreads();

    // ---- top-22 (warp 0), tie-break = lowest index (matches lax.top_k) ----
    if (tid < 32) {
        const int lane = tid;
        for (int r = 0; r < TOPK; r++) {
            float best = -1e30f; int bi = 0x7fffffff;
#pragma unroll 8
            for (int j = 0; j < 64; j++) {
                float v = corrf[(j << 5) + lane];
                if (v > best) { best = v; bi = (j << 5) + lane; }
            }
#pragma unroll
            for (int off = 16; off > 0; off >>= 1) {
                float ov = __shfl_down_sync(0xffffffffu, best, off);
                int   oi = __shfl_down_sync(0xffffffffu, bi, off);
                if (ov > best || (ov == best && oi < bi)) { best = ov; bi = oi; }
            }
            best = __shfl_sync(0xffffffffu, best, 0);
            bi   = __shfl_sync(0xffffffffu, bi, 0);
            if (lane == 0) { topv[r] = best; topd[r] = bi; }
            if ((bi & 31) == lane) corrf[bi] = -1e30f;
            __syncwarp();
        }
        // softmax over the 22 (descending) values
        float e = 0.0f;
        const float mx = topv[0];
        if (lane < TOPK) { e = expf(topv[lane] - mx); wts[lane] = e; }
        float ssum = e;
#pragma unroll
        for (int off = 16; off > 0; off >>= 1)
            ssum += __shfl_down_sync(0xffffffffu, ssum, off);
        ssum = __shfl_sync(0xffffffffu, ssum, 0);
        const float inv = 1.0f / ssum;
        if (lane < 8) vsh[lane] = Vs[(size_t)(((b << 3) + lane) << 10) + c];
        __syncwarp();
        if (lane < 8) {
            float acc = 0.0f;
#pragma unroll
            for (int i = 0; i < TOPK; i++)
                acc += wts[i] * vsh[(lane + topd[i]) & 7];
            Rsmall[(size_t)(((b << 3) + lane) << 10) + c] = acc * inv;
        }
    }
}

// ---------------------------------------------------------------------------
// Broadcast: out[b,l,:] = Tout[b*8 + (l%8), :]
// ---------------------------------------------------------------------------
__global__ void broadcast_out(const float* __restrict__ Tout, float* __restrict__ out)
{
    const size_t idx = (size_t)blockIdx.x * 256 + threadIdx.x;  // < ELEMS
    const int cc = (int)(idx & 1023);
    const int l  = (int)((idx >> 10) & 2047);
    const int bb = (int)(idx >> 21);
    out[idx] = Tout[(size_t)(((bb << 3) + (l & 7)) << 10) + cc];
}

// ---------------------------------------------------------------------------
extern "C" void kernel_launch(void* const* d_in, const int* in_sizes, int n_in,
                              void* d_out, int out_size)
{
    (void)in_sizes; (void)n_in; (void)out_size;
    const float* queries = (const float*)d_in[0];
    const float* keys    = (const float*)d_in[1];
    const float* values  = (const float*)d_in[2];
    const float* Wq = (const float*)d_in[3];
    const float* bq = (const float*)d_in[4];
    const float* Wk = (const float*)d_in[5];
    const float* bk = (const float*)d_in[6];
    const float* Wv = (const float*)d_in[7];
    const float* bv = (const float*)d_in[8];
    const float* Wo = (const float*)d_in[9];
    const float* bo = (const float*)d_in[10];
    float* out = (float*)d_out;

    float *Qb, *Kb, *Qt, *Kt, *corrS, *Vs, *Rs, *To;
    __nv_bfloat16 *Xhi, *Xlo, *Whi, *Wlo;
    float2* twp;
    cudaGetSymbolAddress((void**)&Qb, g_Qb);
    cudaGetSymbolAddress((void**)&Kb, g_Kb);
    cudaGetSymbolAddress((void**)&Qt, g_Qt);
    cudaGetSymbolAddress((void**)&Kt, g_Kt);
    cudaGetSymbolAddress((void**)&corrS, g_corr);
    cudaGetSymbolAddress((void**)&Vs, g_Vs);
    cudaGetSymbolAddress((void**)&Rs, g_Rs);
    cudaGetSymbolAddress((void**)&To, g_To);
    cudaGetSymbolAddress((void**)&Xhi, g_Xhi);
    cudaGetSymbolAddress((void**)&Xlo, g_Xlo);
    cudaGetSymbolAddress((void**)&Whi, g_Whi);
    cudaGetSymbolAddress((void**)&Wlo, g_Wlo);
    cudaGetSymbolAddress((void**)&twp, g_tw);

    fill_tw<<<4, 256>>>(twp);

    dim3 gemmGrid(1024 / 128, (BATCH * SEQ) / 128);  // (8, 128)

    // Q projection on tensor cores (split-bf16, 3 products)
    split_bf16<<<ELEMS / 1024, 256>>>(queries, Xhi, Xlo);
    split_bf16<<<(DIM * DIM) / 1024, 256>>>(Wq, Whi, Wlo);
    gemm_bf16x2<<<gemmGrid, 256>>>(Xhi, Xlo, Whi, Wlo, bq, Qb);

    // K projection
    split_bf16<<<ELEMS / 1024, 256>>>(keys, Xhi, Xlo);
    split_bf16<<<(DIM * DIM) / 1024, 256>>>(Wk, Whi, Wlo);
    gemm_bf16x2<<<gemmGrid, 256>>>(Xhi, Xlo, Whi, Wlo, bk, Kb);

    // V projection: only rows l = 0..7 per batch matter (mod-8 quirk)
    rowgemm64<<<64, 256>>>(values, Wv, bv, Vs, (size_t)SEQ * DIM);

    // [B,L,C] -> [B,C,L]
    transpose_bRC<<<dim3(1024 / 32, 2048 / 32, BATCH), dim3(32, 8)>>>(Qb, Qt, 2048, 1024);
    transpose_bRC<<<dim3(1024 / 32, 2048 / 32, BATCH), dim3(32, 8)>>>(Kb, Kt, 2048, 1024);

    // FFT correlation + top-k + mod-8 aggregation
    fft_corr_topk<<<BATCH * DIM, 256>>>(Qt, Kt, Vs, twp, corrS, Rs);

    // corr [B,C,L] -> second output half [B,L,C]
    transpose_bRC<<<dim3(2048 / 32, 1024 / 32, BATCH), dim3(32, 8)>>>(corrS, out + (size_t)ELEMS, 1024, 2048);

    // out = result @ Wo + bo  (result rows periodic: 64 distinct rows)
    rowgemm64<<<64, 256>>>(Rs, Wo, bo, To, (size_t)8 * DIM);
    broadcast_out<<<ELEMS / 256, 256>>>(To, out);
}

// round 4
// speedup vs baseline: 1.8246x; 1.3186x over previous
#include <cuda_runtime.h>
#include <cuda_bf16.h>
#include <cstdint>
#include <cmath>

// ---------------------------------------------------------------------------
// Problem constants: B=8, L=2048, D=1024 (H=16, E=64 -> C = 1024), topk=22
// ---------------------------------------------------------------------------
#define BATCH 8
#define SEQ   2048
#define DIM   1024
#define TOPK  22
#define ELEMS (BATCH * SEQ * DIM)   // 16777216

// Scratch (allocation-free: __device__ globals)
__device__ float g_Qt[ELEMS];     // Q projected+transposed [B,C,L]
__device__ float g_Kt[ELEMS];     // K projected+transposed [B,C,L]
__device__ float g_corr[ELEMS];   // corr [B,C,L]
__device__ float g_Vs[BATCH * 8 * DIM];  // V rows l=0..7 only
__device__ float g_Rs[BATCH * 8 * DIM];  // aggregated result (periodic rows)
__device__ float g_To[BATCH * 8 * DIM];  // Rs @ Wo + bo
__device__ __nv_bfloat16 g_Xhi[ELEMS];   // split-bf16 staging for activations
__device__ __nv_bfloat16 g_Xlo[ELEMS];
__device__ __nv_bfloat16 g_Whi[DIM * DIM];
__device__ __nv_bfloat16 g_Wlo[DIM * DIM];
__device__ float2 g_tw[1024];            // FFT twiddles exp(+i 2 pi p / 2048)

// ---------------------------------------------------------------------------
// Split fp32 -> (hi, lo) bf16 pair.  x ~= hi + lo with ~17-bit mantissa.
// ---------------------------------------------------------------------------
__global__ void split_bf16(const float* __restrict__ x,
                           __nv_bfloat16* __restrict__ hi,
                           __nv_bfloat16* __restrict__ lo)
{
    const int i = blockIdx.x * 256 + threadIdx.x;  // one float4 per thread
    float4 v = ((const float4*)x)[i];
    float vv[4] = {v.x, v.y, v.z, v.w};
    __nv_bfloat16 h[4], l[4];
#pragma unroll
    for (int j = 0; j < 4; j++) {
        h[j] = __float2bfloat16(vv[j]);
        l[j] = __float2bfloat16(vv[j] - __bfloat162float(h[j]));
    }
    *(uint2*)(hi + 4 * (size_t)i) = *(uint2*)h;
    *(uint2*)(lo + 4 * (size_t)i) = *(uint2*)l;
}

// ---------------------------------------------------------------------------
// Tensor-core GEMM with fused transposed output:
//   T[b, n, l] = (X @ W + bias)[b*2048 + l, n]
// 3-stage cp.async pipeline, one __syncthreads per k-iter, 8 warps (2x4),
// block tile 128x128, k-step 16, bf16 hi/lo split (3 mma products).
// ---------------------------------------------------------------------------
#define APAD 24    // A smem row halves (16 data + 8 pad)
#define BPAD 136   // B smem row halves (128 data + 8 pad)
#define A_BYTES (128 * APAD * 2)          // 6144
#define B_BYTES (16 * BPAD * 2)           // 4352
#define STAGE_BYTES (2 * A_BYTES + 2 * B_BYTES)  // 20992
#define GEMM_DSMEM (3 * STAGE_BYTES)             // 62976

__device__ __forceinline__ void cp16(uint32_t d, const void* s) {
    asm volatile("cp.async.cg.shared.global [%0], [%1], 16;\n" :: "r"(d), "l"(s));
}
__device__ __forceinline__ void cp_commit() { asm volatile("cp.async.commit_group;\n"); }
__device__ __forceinline__ void cp_wait0()  { asm volatile("cp.async.wait_group 0;\n"); }
__device__ __forceinline__ void cp_wait1()  { asm volatile("cp.async.wait_group 1;\n"); }

__device__ __forceinline__ void ldsm4(uint32_t* r, uint32_t a) {
    asm volatile("ldmatrix.sync.aligned.m8n8.x4.shared.b16 {%0,%1,%2,%3},[%4];"
                 : "=r"(r[0]), "=r"(r[1]), "=r"(r[2]), "=r"(r[3]) : "r"(a));
}
__device__ __forceinline__ void ldsm4t(uint32_t* r, uint32_t a) {
    asm volatile("ldmatrix.sync.aligned.m8n8.x4.trans.shared.b16 {%0,%1,%2,%3},[%4];"
                 : "=r"(r[0]), "=r"(r[1]), "=r"(r[2]), "=r"(r[3]) : "r"(a));
}
__device__ __forceinline__ void mma_bf16(float* c, const uint32_t* a, const uint32_t* b) {
    asm volatile("mma.sync.aligned.m16n8k16.row.col.f32.bf16.bf16.f32 "
                 "{%0,%1,%2,%3},{%4,%5,%6,%7},{%8,%9},{%0,%1,%2,%3};"
                 : "+f"(c[0]), "+f"(c[1]), "+f"(c[2]), "+f"(c[3])
                 : "r"(a[0]), "r"(a[1]), "r"(a[2]), "r"(a[3]), "r"(b[0]), "r"(b[1]));
}

__global__ __launch_bounds__(256) void gemm_bf16x2_t(
    const __nv_bfloat16* __restrict__ Ahi, const __nv_bfloat16* __restrict__ Alo,
    const __nv_bfloat16* __restrict__ Bhi, const __nv_bfloat16* __restrict__ Blo,
    const float* __restrict__ bias, float* __restrict__ T)
{
    extern __shared__ __align__(16) char dsm[];

    const int tid = threadIdx.x;
    const int warp = tid >> 5, lane = tid & 31;
    const int wm = warp >> 2, wn = warp & 3;          // 2 x 4 warp grid
    const int m0 = blockIdx.y * 128, n0 = blockIdx.x * 128;

    float acc[4][4][4];
#pragma unroll
    for (int i = 0; i < 4; i++)
#pragma unroll
        for (int j = 0; j < 4; j++)
#pragma unroll
            for (int k = 0; k < 4; k++) acc[i][j][k] = 0.0f;

    const int a_m = tid >> 1, a_c = tid & 1;   // A: 128 rows x 2 16B chunks
    const int b_k = tid >> 4, b_c = tid & 15;  // B: 16 rows x 16 16B chunks

#define SAH(s) ((__nv_bfloat16*)(dsm + (s) * STAGE_BYTES))
#define SAL(s) ((__nv_bfloat16*)(dsm + (s) * STAGE_BYTES + A_BYTES))
#define SBH(s) ((__nv_bfloat16*)(dsm + (s) * STAGE_BYTES + 2 * A_BYTES))
#define SBL(s) ((__nv_bfloat16*)(dsm + (s) * STAGE_BYTES + 2 * A_BYTES + B_BYTES))

#define GEMM_ISSUE(s, k0)                                                            \
    do {                                                                             \
        cp16((uint32_t)__cvta_generic_to_shared(SAH(s) + a_m * APAD + a_c * 8),      \
             Ahi + (size_t)(m0 + a_m) * 1024 + (k0) + a_c * 8);                      \
        cp16((uint32_t)__cvta_generic_to_shared(SAL(s) + a_m * APAD + a_c * 8),      \
             Alo + (size_t)(m0 + a_m) * 1024 + (k0) + a_c * 8);                      \
        cp16((uint32_t)__cvta_generic_to_shared(SBH(s) + b_k * BPAD + b_c * 8),      \
             Bhi + (size_t)((k0) + b_k) * 1024 + n0 + b_c * 8);                      \
        cp16((uint32_t)__cvta_generic_to_shared(SBL(s) + b_k * BPAD + b_c * 8),      \
             Blo + (size_t)((k0) + b_k) * 1024 + n0 + b_c * 8);                      \
        cp_commit();                                                                 \
    } while (0)

    GEMM_ISSUE(0, 0);
    GEMM_ISSUE(1, 16);

    const int ar = lane & 15, ac8 = (lane >> 4) * 8;    // ldmatrix lane addressing

    for (int it = 0; it < 64; it++) {
        if (it == 63) cp_wait0(); else cp_wait1();
        __syncthreads();

        const int s = it % 3;
        uint32_t ah[4][4], al[4][4], bh[4][2], bl[4][2];
#pragma unroll
        for (int mb = 0; mb < 4; mb++) {
            const int row = wm * 64 + mb * 16 + ar;
            ldsm4(ah[mb], (uint32_t)__cvta_generic_to_shared(SAH(s) + row * APAD + ac8));
            ldsm4(al[mb], (uint32_t)__cvta_generic_to_shared(SAL(s) + row * APAD + ac8));
        }
#pragma unroll
        for (int nb2 = 0; nb2 < 2; nb2++) {
            uint32_t r[4];
            const int col = wn * 32 + nb2 * 16 + ac8;
            ldsm4t(r, (uint32_t)__cvta_generic_to_shared(SBH(s) + ar * BPAD + col));
            bh[nb2 * 2][0] = r[0]; bh[nb2 * 2][1] = r[1];
            bh[nb2 * 2 + 1][0] = r[2]; bh[nb2 * 2 + 1][1] = r[3];
            ldsm4t(r, (uint32_t)__cvta_generic_to_shared(SBL(s) + ar * BPAD + col));
            bl[nb2 * 2][0] = r[0]; bl[nb2 * 2][1] = r[1];
            bl[nb2 * 2 + 1][0] = r[2]; bl[nb2 * 2 + 1][1] = r[3];
        }
#pragma unroll
        for (int mb = 0; mb < 4; mb++)
#pragma unroll
            for (int nb = 0; nb < 4; nb++) {
                mma_bf16(acc[mb][nb], ah[mb], bh[nb]);   // hi*hi
                mma_bf16(acc[mb][nb], ah[mb], bl[nb]);   // hi*lo
                mma_bf16(acc[mb][nb], al[mb], bh[nb]);   // lo*hi
            }

        if (it + 2 < 64) GEMM_ISSUE((it + 2) % 3, (it + 2) * 16);
    }

    // ---- Fused transposed epilogue: write T[b, c, l] (coalesced along l) ----
    // Stage 64 output columns at a time in smem as sT[c_local][m], pad 132.
    float* sT = (float*)dsm;                 // 64 * 132 * 4 = 33792 B (fits)
    const int g = lane >> 2, t2 = (lane & 3) * 2;
    const int l0 = m0 & 2047;
    const int bq = m0 >> 11;

#pragma unroll
    for (int p = 0; p < 2; p++) {
        __syncthreads();
        if ((wn >> 1) == p) {
            const int chalf = (wn & 1) * 32;
#pragma unroll
            for (int mb = 0; mb < 4; mb++) {
                const int row = wm * 64 + mb * 16 + g;
#pragma unroll
                for (int nb = 0; nb < 4; nb++) {
                    const int cl = chalf + nb * 8 + t2;
                    const int cgl = n0 + p * 64 + cl;
                    const float b0 = bias[cgl], b1 = bias[cgl + 1];
                    sT[cl * 132 + row]           = acc[mb][nb][0] + b0;
                    sT[(cl + 1) * 132 + row]     = acc[mb][nb][1] + b1;
                    sT[cl * 132 + row + 8]       = acc[mb][nb][2] + b0;
                    sT[(cl + 1) * 132 + row + 8] = acc[mb][nb][3] + b1;
                }
            }
        }
        __syncthreads();
        const size_t cb = (size_t)bq * 1024 + n0 + p * 64;
#pragma unroll
        for (int i = tid; i < 2048; i += 256) {     // 64 c x 32 float4
            const int c = i >> 5, m4 = (i & 31) << 2;
            float4 v = *(float4*)&sT[c * 132 + m4];
            *(float4*)&T[((cb + c) << 11) + l0 + m4] = v;
        }
    }
}

// ---------------------------------------------------------------------------
// Small GEMM, coalesced: Y[64,1024] = X[64,1024] @ W + bias.
// Row r of X maps to X + (r/8)*b_stride + (r%8)*1024.
// Grid 64 blocks: block handles all 64 rows x 16 cols. W read exactly once.
// ---------------------------------------------------------------------------
__global__ __launch_bounds__(256) void rowgemm64(
    const float* __restrict__ X, const float* __restrict__ W,
    const float* __restrict__ bias, float* __restrict__ Y, size_t b_stride)
{
    __shared__ float Xs[64][128];     // 32 KB
    __shared__ float Ws[16][129];     // transposed [n][k], pad 129 (conflict-free)

    const int tid = threadIdx.x;
    const int n0 = blockIdx.x * 16;
    const int n = tid & 15, rg = tid >> 4;   // 16 row-groups x 4 rows

    float a0 = 0.f, a1 = 0.f, a2 = 0.f, a3 = 0.f;

    for (int kt = 0; kt < 8; kt++) {
#pragma unroll
        for (int j = 0; j < 8; j++) {                 // X tile: 2048 float4
            const int i = tid + j * 256;
            const int row = i >> 5, c4 = (i & 31) << 2;
            const float* xr = X + (size_t)(row >> 3) * b_stride + (size_t)(row & 7) * 1024;
            *(float4*)&Xs[row][c4] = *(const float4*)(xr + kt * 128 + c4);
        }
#pragma unroll
        for (int j = 0; j < 8; j++) {                 // W tile: 128k x 16n -> Ws[n][k]
            const int i = tid + j * 256;
            const int k = i >> 4, nn = i & 15;
            Ws[nn][k] = W[(size_t)(kt * 128 + k) * 1024 + n0 + nn];
        }
        __syncthreads();
#pragma unroll 4
        for (int k = 0; k < 128; k++) {
            const float w = Ws[n][k];
            a0 += Xs[rg * 4 + 0][k] * w;
            a1 += Xs[rg * 4 + 1][k] * w;
            a2 += Xs[rg * 4 + 2][k] * w;
            a3 += Xs[rg * 4 + 3][k] * w;
        }
        __syncthreads();
    }
    const float bb = bias[n0 + n];
    Y[(size_t)(rg * 4 + 0) * 1024 + n0 + n] = a0 + bb;
    Y[(size_t)(rg * 4 + 1) * 1024 + n0 + n] = a1 + bb;
    Y[(size_t)(rg * 4 + 2) * 1024 + n0 + n] = a2 + bb;
    Y[(size_t)(rg * 4 + 3) * 1024 + n0 + n] = a3 + bb;
}

// ---------------------------------------------------------------------------
// Batched 2D transpose: out[b, j, i] = in[b, i, j], i<R, j<C (R,C mult of 32)
// ---------------------------------------------------------------------------
__global__ void transpose_bRC(const float* __restrict__ in, float* __restrict__ out,
                              int R, int C)
{
    __shared__ float tile[32][33];
    const int bz = blockIdx.z;
    const float* ip = in + (size_t)bz * R * C;
    float* op = out + (size_t)bz * R * C;
    const int j0 = blockIdx.x * 32;
    const int i0 = blockIdx.y * 32;
    const int tx = threadIdx.x, ty = threadIdx.y;
#pragma unroll
    for (int k = 0; k < 4; k++)
        tile[ty + k * 8][tx] = ip[(size_t)(i0 + ty + k * 8) * C + (j0 + tx)];
    __syncthreads();
#pragma unroll
    for (int k = 0; k < 4; k++)
        op[(size_t)(j0 + ty + k * 8) * R + (i0 + tx)] = tile[tx][ty + k * 8];
}

// ---------------------------------------------------------------------------
// FFT twiddle table: g_tw[p] = (cos, sin)(2 pi p / 2048), p < 1024
// ---------------------------------------------------------------------------
__global__ void fill_tw(float2* tw)
{
    const int i = blockIdx.x * 256 + threadIdx.x;
    if (i < 1024) {
        float s, c;
        sincosf(6.28318530717958647692f * (float)i / 2048.0f, &s, &c);
        tw[i] = make_float2(c, s);
    }
}

// ---------------------------------------------------------------------------
// In-shared-memory Stockham radix-2 FFT, N=2048, 256 threads, global twiddles
// (L1-broadcast friendly).  Forward: sign=-1.  Inverse (unnormalized): +1.
// ---------------------------------------------------------------------------
__device__ __forceinline__ void fft2048_stages(float2* __restrict__ A,
                                               float2* __restrict__ B,
                                               const float2* __restrict__ twg,
                                               int tid, float sign)
{
    float2* x = A;
    float2* y = B;
#pragma unroll
    for (int st = 0; st < 11; st++) {
        const int ls = st;
#pragma unroll
        for (int u = 0; u < 4; u++) {
            const int idx = tid + (u << 8);       // 0..1023
            const int p = idx >> ls;
            float2 a  = x[idx];
            float2 b2 = x[idx + 1024];
            float2 w  = __ldg(&twg[(p << ls) & 1023]);
            const float co = w.x, si = sign * w.y;
            float2 s = make_float2(a.x + b2.x, a.y + b2.y);
            float2 d = make_float2(a.x - b2.x, a.y - b2.y);
            float2 t = make_float2(d.x * co - d.y * si, d.x * si + d.y * co);
            const int w0 = idx + (p << ls);
            y[w0] = s;
            y[w0 + (1 << ls)] = t;
        }
        __syncthreads();
        float2* tmp = x; x = y; y = tmp;
    }
}

// ---------------------------------------------------------------------------
// Per-(b,c) kernel: packed FFT correlation -> corr, then top-22 + softmax +
// mod-8 V aggregation (agg is periodic in l with period 8).
// ---------------------------------------------------------------------------
__global__ __launch_bounds__(256) void fft_corr_topk(
    const float* __restrict__ Qt, const float* __restrict__ Kt,
    const float* __restrict__ Vs, const float2* __restrict__ twg,
    float* __restrict__ corrS, float* __restrict__ Rsmall)
{
    __shared__ float2 SA[2048];
    __shared__ float2 SB[2048];
    __shared__ float topv[TOPK];
    __shared__ int   topd[TOPK];
    __shared__ float wts[TOPK];
    __shared__ float vsh[8];

    const int tid = threadIdx.x;
    const int bidx = blockIdx.x;              // b*1024 + c
    const int b = bidx >> 10;
    const int c = bidx & 1023;

    const float* qp = Qt + (size_t)bidx * 2048;
    const float* kp = Kt + (size_t)bidx * 2048;
    for (int l = tid; l < 2048; l += 256) SA[l] = make_float2(qp[l], kp[l]);
    __syncthreads();

    // Forward FFT of z = q + i*k  -> Z in SB
    fft2048_stages(SA, SB, twg, tid, -1.0f);

    // P[f] = Q[f]*conj(K[f]) = 0.25i * (a + conj(b)) * (conj(a) - b)
    for (int f = tid; f < 2048; f += 256) {
        float2 a  = SB[f];
        float2 bz = SB[(2048 - f) & 2047];
        float ux = a.x + bz.x, uy = a.y - bz.y;
        float vx = a.x - bz.x, vy = -a.y - bz.y;
        float pr = ux * vx - uy * vy;
        float pi = ux * vy + uy * vx;
        SA[f] = make_float2(-0.25f * pi, 0.25f * pr);
    }
    __syncthreads();

    // Inverse FFT of P -> SB (real part * 1/N is corr)
    fft2048_stages(SA, SB, twg, tid, +1.0f);

    float* corrf = (float*)SA;  // SA free now; reuse as float array
    const float invN = 1.0f / 2048.0f;
    float* cg = corrS + (size_t)bidx * 2048;
    for (int n = tid; n < 2048; n += 256) {
        float v = SB[n].x * invN;
        corrf[n] = v;
        cg[n] = v;
    }
    __syncthreads();

    // ---- top-22 (warp 0), tie-break = lowest index (matches lax.top_k) ----
    if (tid < 32) {
        const int lane = tid;
        for (int r = 0; r < TOPK; r++) {
            float best = -1e30f; int bi = 0x7fffffff;
#pragma unroll 8
            for (int j = 0; j < 64; j++) {
                float v = corrf[(j << 5) + lane];
                if (v > best) { best = v; bi = (j << 5) + lane; }
            }
#pragma unroll
            for (int off = 16; off > 0; off >>= 1) {
                float ov = __shfl_down_sync(0xffffffffu, best, off);
                int   oi = __shfl_down_sync(0xffffffffu, bi, off);
                if (ov > best || (ov == best && oi < bi)) { best = ov; bi = oi; }
            }
            best = __shfl_sync(0xffffffffu, best, 0);
            bi   = __shfl_sync(0xffffffffu, bi, 0);
            if (lane == 0) { topv[r] = best; topd[r] = bi; }
            if ((bi & 31) == lane) corrf[bi] = -1e30f;
            __syncwarp();
        }
        // softmax over the 22 (descending) values
        float e = 0.0f;
        const float mx = topv[0];
        if (lane < TOPK) { e = expf(topv[lane] - mx); wts[lane] = e; }
        float ssum = e;
#pragma unroll
        for (int off = 16; off > 0; off >>= 1)
            ssum += __shfl_down_sync(0xffffffffu, ssum, off);
        ssum = __shfl_sync(0xffffffffu, ssum, 0);
        const float inv = 1.0f / ssum;
        if (lane < 8) vsh[lane] = Vs[(size_t)(((b << 3) + lane) << 10) + c];
        __syncwarp();
        if (lane < 8) {
            float acc = 0.0f;
#pragma unroll
            for (int i = 0; i < TOPK; i++)
                acc += wts[i] * vsh[(lane + topd[i]) & 7];
            Rsmall[(size_t)(((b << 3) + lane) << 10) + c] = acc * inv;
        }
    }
}

// ---------------------------------------------------------------------------
// Broadcast: out[b,l,:] = Tout[b*8 + (l%8), :]
// ---------------------------------------------------------------------------
__global__ void broadcast_out(const float* __restrict__ Tout, float* __restrict__ out)
{
    const size_t idx = (size_t)blockIdx.x * 256 + threadIdx.x;  // < ELEMS
    const int cc = (int)(idx & 1023);
    const int l  = (int)((idx >> 10) & 2047);
    const int bb = (int)(idx >> 21);
    out[idx] = Tout[(size_t)(((bb << 3) + (l & 7)) << 10) + cc];
}

// ---------------------------------------------------------------------------
extern "C" void kernel_launch(void* const* d_in, const int* in_sizes, int n_in,
                              void* d_out, int out_size)
{
    (void)in_sizes; (void)n_in; (void)out_size;
    const float* queries = (const float*)d_in[0];
    const float* keys    = (const float*)d_in[1];
    const float* values  = (const float*)d_in[2];
    const float* Wq = (const float*)d_in[3];
    const float* bq = (const float*)d_in[4];
    const float* Wk = (const float*)d_in[5];
    const float* bk = (const float*)d_in[6];
    const float* Wv = (const float*)d_in[7];
    const float* bv = (const float*)d_in[8];
    const float* Wo = (const float*)d_in[9];
    const float* bo = (const float*)d_in[10];
    float* out = (float*)d_out;

    float *Qt, *Kt, *corrS, *Vs, *Rs, *To;
    __nv_bfloat16 *Xhi, *Xlo, *Whi, *Wlo;
    float2* twp;
    cudaGetSymbolAddress((void**)&Qt, g_Qt);
    cudaGetSymbolAddress((void**)&Kt, g_Kt);
    cudaGetSymbolAddress((void**)&corrS, g_corr);
    cudaGetSymbolAddress((void**)&Vs, g_Vs);
    cudaGetSymbolAddress((void**)&Rs, g_Rs);
    cudaGetSymbolAddress((void**)&To, g_To);
    cudaGetSymbolAddress((void**)&Xhi, g_Xhi);
    cudaGetSymbolAddress((void**)&Xlo, g_Xlo);
    cudaGetSymbolAddress((void**)&Whi, g_Whi);
    cudaGetSymbolAddress((void**)&Wlo, g_Wlo);
    cudaGetSymbolAddress((void**)&twp, g_tw);

    static int attr_done = 0;
    if (!attr_done) {
        cudaFuncSetAttribute(gemm_bf16x2_t,
                             cudaFuncAttributeMaxDynamicSharedMemorySize, GEMM_DSMEM);
        attr_done = 1;
    }

    fill_tw<<<4, 256>>>(twp);

    dim3 gemmGrid(1024 / 128, (BATCH * SEQ) / 128);  // (8, 128)

    // Q projection on tensor cores (split-bf16, 3 products), writes Qt directly
    split_bf16<<<ELEMS / 1024, 256>>>(queries, Xhi, Xlo);
    split_bf16<<<(DIM * DIM) / 1024, 256>>>(Wq, Whi, Wlo);
    gemm_bf16x2_t<<<gemmGrid, 256, GEMM_DSMEM>>>(Xhi, Xlo, Whi, Wlo, bq, Qt);

    // K projection, writes Kt directly
    split_bf16<<<ELEMS / 1024, 256>>>(keys, Xhi, Xlo);
    split_bf16<<<(DIM * DIM) / 1024, 256>>>(Wk, Whi, Wlo);
    gemm_bf16x2_t<<<gemmGrid, 256, GEMM_DSMEM>>>(Xhi, Xlo, Whi, Wlo, bk, Kt);

    // V projection: only rows l = 0..7 per batch matter (mod-8 quirk)
    rowgemm64<<<64, 256>>>(values, Wv, bv, Vs, (size_t)SEQ * DIM);

    // FFT correlation + top-k + mod-8 aggregation
    fft_corr_topk<<<BATCH * DIM, 256>>>(Qt, Kt, Vs, twp, corrS, Rs);

    // corr [B,C,L] -> second output half [B,L,C]
    transpose_bRC<<<dim3(2048 / 32, 1024 / 32, BATCH), dim3(32, 8)>>>(corrS, out + (size_t)ELEMS, 1024, 2048);

    // out = result @ Wo + bo  (result rows periodic: 64 distinct rows)
    rowgemm64<<<64, 256>>>(Rs, Wo, bo, To, (size_t)8 * DIM);
    broadcast_out<<<ELEMS / 256, 256>>>(To, out);
}

// round 5
// speedup vs baseline: 2.5055x; 1.3732x over previous
#include <cuda_runtime.h>
#include <cuda_bf16.h>
#include <cstdint>
#include <cmath>

// ---------------------------------------------------------------------------
// Problem constants: B=8, L=2048, D=1024 (H=16, E=64 -> C = 1024), topk=22
// ---------------------------------------------------------------------------
#define BATCH 8
#define SEQ   2048
#define DIM   1024
#define TOPK  22
#define ELEMS (BATCH * SEQ * DIM)   // 16777216

// Scratch (allocation-free: __device__ globals)
__device__ float g_Qt[ELEMS];     // Q projected+transposed [B,C,L]
__device__ float g_Kt[ELEMS];     // K projected+transposed [B,C,L]
__device__ float g_corr[ELEMS];   // corr [B,C,L]
__device__ float g_Vs[BATCH * 8 * DIM];  // V rows l=0..7 only
__device__ float g_Rs[BATCH * 8 * DIM];  // aggregated result (periodic rows)
__device__ float g_To[BATCH * 8 * DIM];  // Rs @ Wo + bo
__device__ __nv_bfloat16 g_Xhi[ELEMS];   // split-bf16 staging for activations
__device__ __nv_bfloat16 g_Xlo[ELEMS];
__device__ __nv_bfloat16 g_Whi[DIM * DIM];
__device__ __nv_bfloat16 g_Wlo[DIM * DIM];
__device__ float2 g_tw[1024];            // FFT twiddles exp(+i 2 pi p / 2048)

// ---------------------------------------------------------------------------
// Split fp32 -> (hi, lo) bf16 pair.  x ~= hi + lo with ~17-bit mantissa.
// ---------------------------------------------------------------------------
__global__ void split_bf16(const float* __restrict__ x,
                           __nv_bfloat16* __restrict__ hi,
                           __nv_bfloat16* __restrict__ lo)
{
    const int i = blockIdx.x * 256 + threadIdx.x;  // one float4 per thread
    float4 v = ((const float4*)x)[i];
    float vv[4] = {v.x, v.y, v.z, v.w};
    __nv_bfloat16 h[4], l[4];
#pragma unroll
    for (int j = 0; j < 4; j++) {
        h[j] = __float2bfloat16(vv[j]);
        l[j] = __float2bfloat16(vv[j] - __bfloat162float(h[j]));
    }
    *(uint2*)(hi + 4 * (size_t)i) = *(uint2*)h;
    *(uint2*)(lo + 4 * (size_t)i) = *(uint2*)l;
}

// ---------------------------------------------------------------------------
// Tensor-core GEMM with fused transposed output:
//   T[b, n, l] = (X @ W + bias)[b*2048 + l, n]
// 3-stage cp.async pipeline, one __syncthreads per k-iter, 8 warps (2x4),
// block tile 128x128, k-step 16, bf16 hi/lo split (3 mma products).
// ---------------------------------------------------------------------------
#define APAD 24    // A smem row halves (16 data + 8 pad)
#define BPAD 136   // B smem row halves (128 data + 8 pad)
#define A_BYTES (128 * APAD * 2)          // 6144
#define B_BYTES (16 * BPAD * 2)           // 4352
#define STAGE_BYTES (2 * A_BYTES + 2 * B_BYTES)  // 20992
#define GEMM_DSMEM (3 * STAGE_BYTES)             // 62976

__device__ __forceinline__ void cp16(uint32_t d, const void* s) {
    asm volatile("cp.async.cg.shared.global [%0], [%1], 16;\n" :: "r"(d), "l"(s));
}
__device__ __forceinline__ void cp_commit() { asm volatile("cp.async.commit_group;\n"); }
__device__ __forceinline__ void cp_wait0()  { asm volatile("cp.async.wait_group 0;\n"); }
__device__ __forceinline__ void cp_wait1()  { asm volatile("cp.async.wait_group 1;\n"); }

__device__ __forceinline__ void ldsm4(uint32_t* r, uint32_t a) {
    asm volatile("ldmatrix.sync.aligned.m8n8.x4.shared.b16 {%0,%1,%2,%3},[%4];"
                 : "=r"(r[0]), "=r"(r[1]), "=r"(r[2]), "=r"(r[3]) : "r"(a));
}
__device__ __forceinline__ void ldsm4t(uint32_t* r, uint32_t a) {
    asm volatile("ldmatrix.sync.aligned.m8n8.x4.trans.shared.b16 {%0,%1,%2,%3},[%4];"
                 : "=r"(r[0]), "=r"(r[1]), "=r"(r[2]), "=r"(r[3]) : "r"(a));
}
__device__ __forceinline__ void mma_bf16(float* c, const uint32_t* a, const uint32_t* b) {
    asm volatile("mma.sync.aligned.m16n8k16.row.col.f32.bf16.bf16.f32 "
                 "{%0,%1,%2,%3},{%4,%5,%6,%7},{%8,%9},{%0,%1,%2,%3};"
                 : "+f"(c[0]), "+f"(c[1]), "+f"(c[2]), "+f"(c[3])
                 : "r"(a[0]), "r"(a[1]), "r"(a[2]), "r"(a[3]), "r"(b[0]), "r"(b[1]));
}

__global__ __launch_bounds__(256) void gemm_bf16x2_t(
    const __nv_bfloat16* __restrict__ Ahi, const __nv_bfloat16* __restrict__ Alo,
    const __nv_bfloat16* __restrict__ Bhi, const __nv_bfloat16* __restrict__ Blo,
    const float* __restrict__ bias, float* __restrict__ T)
{
    extern __shared__ __align__(16) char dsm[];

    const int tid = threadIdx.x;
    const int warp = tid >> 5, lane = tid & 31;
    const int wm = warp >> 2, wn = warp & 3;          // 2 x 4 warp grid
    const int m0 = blockIdx.y * 128, n0 = blockIdx.x * 128;

    float acc[4][4][4];
#pragma unroll
    for (int i = 0; i < 4; i++)
#pragma unroll
        for (int j = 0; j < 4; j++)
#pragma unroll
            for (int k = 0; k < 4; k++) acc[i][j][k] = 0.0f;

    const int a_m = tid >> 1, a_c = tid & 1;   // A: 128 rows x 2 16B chunks
    const int b_k = tid >> 4, b_c = tid & 15;  // B: 16 rows x 16 16B chunks

#define SAH(s) ((__nv_bfloat16*)(dsm + (s) * STAGE_BYTES))
#define SAL(s) ((__nv_bfloat16*)(dsm + (s) * STAGE_BYTES + A_BYTES))
#define SBH(s) ((__nv_bfloat16*)(dsm + (s) * STAGE_BYTES + 2 * A_BYTES))
#define SBL(s) ((__nv_bfloat16*)(dsm + (s) * STAGE_BYTES + 2 * A_BYTES + B_BYTES))

#define GEMM_ISSUE(s, k0)                                                            \
    do {                                                                             \
        cp16((uint32_t)__cvta_generic_to_shared(SAH(s) + a_m * APAD + a_c * 8),      \
             Ahi + (size_t)(m0 + a_m) * 1024 + (k0) + a_c * 8);                      \
        cp16((uint32_t)__cvta_generic_to_shared(SAL(s) + a_m * APAD + a_c * 8),      \
             Alo + (size_t)(m0 + a_m) * 1024 + (k0) + a_c * 8);                      \
        cp16((uint32_t)__cvta_generic_to_shared(SBH(s) + b_k * BPAD + b_c * 8),      \
             Bhi + (size_t)((k0) + b_k) * 1024 + n0 + b_c * 8);                      \
        cp16((uint32_t)__cvta_generic_to_shared(SBL(s) + b_k * BPAD + b_c * 8),      \
             Blo + (size_t)((k0) + b_k) * 1024 + n0 + b_c * 8);                      \
        cp_commit();                                                                 \
    } while (0)

    GEMM_ISSUE(0, 0);
    GEMM_ISSUE(1, 16);

    const int ar = lane & 15, ac8 = (lane >> 4) * 8;    // ldmatrix lane addressing

    for (int it = 0; it < 64; it++) {
        if (it == 63) cp_wait0(); else cp_wait1();
        __syncthreads();

        const int s = it % 3;
        uint32_t ah[4][4], al[4][4], bh[4][2], bl[4][2];
#pragma unroll
        for (int mb = 0; mb < 4; mb++) {
            const int row = wm * 64 + mb * 16 + ar;
            ldsm4(ah[mb], (uint32_t)__cvta_generic_to_shared(SAH(s) + row * APAD + ac8));
            ldsm4(al[mb], (uint32_t)__cvta_generic_to_shared(SAL(s) + row * APAD + ac8));
        }
#pragma unroll
        for (int nb2 = 0; nb2 < 2; nb2++) {
            uint32_t r[4];
            const int col = wn * 32 + nb2 * 16 + ac8;
            ldsm4t(r, (uint32_t)__cvta_generic_to_shared(SBH(s) + ar * BPAD + col));
            bh[nb2 * 2][0] = r[0]; bh[nb2 * 2][1] = r[1];
            bh[nb2 * 2 + 1][0] = r[2]; bh[nb2 * 2 + 1][1] = r[3];
            ldsm4t(r, (uint32_t)__cvta_generic_to_shared(SBL(s) + ar * BPAD + col));
            bl[nb2 * 2][0] = r[0]; bl[nb2 * 2][1] = r[1];
            bl[nb2 * 2 + 1][0] = r[2]; bl[nb2 * 2 + 1][1] = r[3];
        }
#pragma unroll
        for (int mb = 0; mb < 4; mb++)
#pragma unroll
            for (int nb = 0; nb < 4; nb++) {
                mma_bf16(acc[mb][nb], ah[mb], bh[nb]);   // hi*hi
                mma_bf16(acc[mb][nb], ah[mb], bl[nb]);   // hi*lo
                mma_bf16(acc[mb][nb], al[mb], bh[nb]);   // lo*hi
            }

        if (it + 2 < 64) GEMM_ISSUE((it + 2) % 3, (it + 2) * 16);
    }

    // ---- Fused transposed epilogue: write T[b, c, l] (coalesced along l) ----
    float* sT = (float*)dsm;                 // 64 * 132 * 4 = 33792 B (fits)
    const int g = lane >> 2, t2 = (lane & 3) * 2;
    const int l0 = m0 & 2047;
    const int bq = m0 >> 11;

#pragma unroll
    for (int p = 0; p < 2; p++) {
        __syncthreads();
        if ((wn >> 1) == p) {
            const int chalf = (wn & 1) * 32;
#pragma unroll
            for (int mb = 0; mb < 4; mb++) {
                const int row = wm * 64 + mb * 16 + g;
#pragma unroll
                for (int nb = 0; nb < 4; nb++) {
                    const int cl = chalf + nb * 8 + t2;
                    const int cgl = n0 + p * 64 + cl;
                    const float b0 = bias[cgl], b1 = bias[cgl + 1];
                    sT[cl * 132 + row]           = acc[mb][nb][0] + b0;
                    sT[(cl + 1) * 132 + row]     = acc[mb][nb][1] + b1;
                    sT[cl * 132 + row + 8]       = acc[mb][nb][2] + b0;
                    sT[(cl + 1) * 132 + row + 8] = acc[mb][nb][3] + b1;
                }
            }
        }
        __syncthreads();
        const size_t cb = (size_t)bq * 1024 + n0 + p * 64;
#pragma unroll
        for (int i = tid; i < 2048; i += 256) {     // 64 c x 32 float4
            const int c = i >> 5, m4 = (i & 31) << 2;
            float4 v = *(float4*)&sT[c * 132 + m4];
            *(float4*)&T[((cb + c) << 11) + l0 + m4] = v;
        }
    }
}

// ---------------------------------------------------------------------------
// Small GEMM, coalesced: Y[64,1024] = X[64,1024] @ W + bias.
// Row r of X maps to X + (r/8)*b_stride + (r%8)*1024.
// ---------------------------------------------------------------------------
__global__ __launch_bounds__(256) void rowgemm64(
    const float* __restrict__ X, const float* __restrict__ W,
    const float* __restrict__ bias, float* __restrict__ Y, size_t b_stride)
{
    __shared__ float Xs[64][128];     // 32 KB
    __shared__ float Ws[16][129];

    const int tid = threadIdx.x;
    const int n0 = blockIdx.x * 16;
    const int n = tid & 15, rg = tid >> 4;   // 16 row-groups x 4 rows

    float a0 = 0.f, a1 = 0.f, a2 = 0.f, a3 = 0.f;

    for (int kt = 0; kt < 8; kt++) {
#pragma unroll
        for (int j = 0; j < 8; j++) {                 // X tile: 2048 float4
            const int i = tid + j * 256;
            const int row = i >> 5, c4 = (i & 31) << 2;
            const float* xr = X + (size_t)(row >> 3) * b_stride + (size_t)(row & 7) * 1024;
            *(float4*)&Xs[row][c4] = *(const float4*)(xr + kt * 128 + c4);
        }
#pragma unroll
        for (int j = 0; j < 8; j++) {                 // W tile: 128k x 16n -> Ws[n][k]
            const int i = tid + j * 256;
            const int k = i >> 4, nn = i & 15;
            Ws[nn][k] = W[(size_t)(kt * 128 + k) * 1024 + n0 + nn];
        }
        __syncthreads();
#pragma unroll 4
        for (int k = 0; k < 128; k++) {
            const float w = Ws[n][k];
            a0 += Xs[rg * 4 + 0][k] * w;
            a1 += Xs[rg * 4 + 1][k] * w;
            a2 += Xs[rg * 4 + 2][k] * w;
            a3 += Xs[rg * 4 + 3][k] * w;
        }
        __syncthreads();
    }
    const float bb = bias[n0 + n];
    Y[(size_t)(rg * 4 + 0) * 1024 + n0 + n] = a0 + bb;
    Y[(size_t)(rg * 4 + 1) * 1024 + n0 + n] = a1 + bb;
    Y[(size_t)(rg * 4 + 2) * 1024 + n0 + n] = a2 + bb;
    Y[(size_t)(rg * 4 + 3) * 1024 + n0 + n] = a3 + bb;
}

// ---------------------------------------------------------------------------
// Batched 2D transpose: out[b, j, i] = in[b, i, j], i<R, j<C (R,C mult of 32)
// ---------------------------------------------------------------------------
__global__ void transpose_bRC(const float* __restrict__ in, float* __restrict__ out,
                              int R, int C)
{
    __shared__ float tile[32][33];
    const int bz = blockIdx.z;
    const float* ip = in + (size_t)bz * R * C;
    float* op = out + (size_t)bz * R * C;
    const int j0 = blockIdx.x * 32;
    const int i0 = blockIdx.y * 32;
    const int tx = threadIdx.x, ty = threadIdx.y;
#pragma unroll
    for (int k = 0; k < 4; k++)
        tile[ty + k * 8][tx] = ip[(size_t)(i0 + ty + k * 8) * C + (j0 + tx)];
    __syncthreads();
#pragma unroll
    for (int k = 0; k < 4; k++)
        op[(size_t)(j0 + ty + k * 8) * R + (i0 + tx)] = tile[tx][ty + k * 8];
}

// ---------------------------------------------------------------------------
// FFT twiddle table: g_tw[p] = (cos, sin)(2 pi p / 2048), p < 1024
// ---------------------------------------------------------------------------
__global__ void fill_tw(float2* tw)
{
    const int i = blockIdx.x * 256 + threadIdx.x;
    if (i < 1024) {
        float s, c;
        sincosf(6.28318530717958647692f * (float)i / 2048.0f, &s, &c);
        tw[i] = make_float2(c, s);
    }
}

// ---------------------------------------------------------------------------
// Radix-4 Stockham FFT, N=2048: 5 radix-4 stages + 1 twiddle-free radix-2.
// Input in `A`, result lands back in `A` (uses `B` as ping-pong scratch).
// Twiddle convention: w = exp(sign * 2*pi*i * e / 2048), tw[e] = (cos,sin).
// ---------------------------------------------------------------------------
__device__ __forceinline__ void fft2048_r4(float2* __restrict__ A,
                                           float2* __restrict__ B,
                                           const float2* __restrict__ twg,
                                           int tid, float sign)
{
    float2* a = A;
    float2* b = B;
#pragma unroll
    for (int t = 0; t < 5; t++) {
        const int ts = 2 * t;
        const int s = 1 << ts;               // 4^t
#pragma unroll
        for (int u = 0; u < 2; u++) {
            const int idx = tid + (u << 8);  // 0..511
            const int q = idx & (s - 1);
            const int p = idx >> ts;
            const int bi = q + (p << ts);    // q + s*p
            float2 x0 = a[bi];
            float2 x1 = a[bi + 512];
            float2 x2 = a[bi + 1024];
            float2 x3 = a[bi + 1536];
            const int e = p << ts;           // p*s  (< 512)
            float2 w1 = __ldg(&twg[e]);
            float2 w2 = __ldg(&twg[2 * e]);  // < 1024
            const float c1 = w1.x, s1 = sign * w1.y;
            const float c2 = w2.x, s2 = sign * w2.y;
            const float c3 = c1 * c2 - s1 * s2, s3 = c1 * s2 + s1 * c2;
            const float apcx = x0.x + x2.x, apcy = x0.y + x2.y;
            const float amcx = x0.x - x2.x, amcy = x0.y - x2.y;
            const float bpdx = x1.x + x3.x, bpdy = x1.y + x3.y;
            const float bmdx = x1.x - x3.x, bmdy = x1.y - x3.y;
            const float t1x = amcx - sign * bmdy, t1y = amcy + sign * bmdx;
            const float t2x = apcx - bpdx,        t2y = apcy - bpdy;
            const float t3x = amcx + sign * bmdy, t3y = amcy - sign * bmdx;
            const int ob = q + (p << (ts + 2));  // q + s*4p
            b[ob]         = make_float2(apcx + bpdx, apcy + bpdy);
            b[ob + s]     = make_float2(t1x * c1 - t1y * s1, t1x * s1 + t1y * c1);
            b[ob + 2 * s] = make_float2(t2x * c2 - t2y * s2, t2x * s2 + t2y * c2);
            b[ob + 3 * s] = make_float2(t3x * c3 - t3y * s3, t3x * s3 + t3y * c3);
        }
        __syncthreads();
        float2* tmp = a; a = b; b = tmp;
    }
    // Final radix-2 (s=1024, n=2, twiddle = 1): reads a(==B'), writes b(==A').
#pragma unroll
    for (int u = 0; u < 4; u++) {
        const int idx = tid + (u << 8);      // 0..1023
        float2 x0 = a[idx], x1 = a[idx + 1024];
        b[idx]        = make_float2(x0.x + x1.x, x0.y + x1.y);
        b[idx + 1024] = make_float2(x0.x - x1.x, x0.y - x1.y);
    }
    __syncthreads();
    // result now in A (b pointer == A after 5 swaps)
}

// ---------------------------------------------------------------------------
// Per-(b,c) kernel: packed radix-4 FFT correlation -> corr, then parallel
// register-resident top-22 + softmax + mod-8 V aggregation.
// ---------------------------------------------------------------------------
__global__ __launch_bounds__(256) void fft_corr_topk(
    const float* __restrict__ Qt, const float* __restrict__ Kt,
    const float* __restrict__ Vs, const float2* __restrict__ twg,
    float* __restrict__ corrS, float* __restrict__ Rsmall)
{
    __shared__ float2 SA[2048];
    __shared__ float2 SB[2048];
    __shared__ float topv[TOPK];
    __shared__ int   topd[TOPK];
    __shared__ float wts[TOPK];
    __shared__ float vsh[8];
    __shared__ float wv[8];
    __shared__ int   wi[8];
    __shared__ int   bcast;

    const int tid = threadIdx.x;
    const int lane = tid & 31, warp = tid >> 5;
    const int bidx = blockIdx.x;              // b*1024 + c
    const int b = bidx >> 10;
    const int c = bidx & 1023;

    const float* qp = Qt + (size_t)bidx * 2048;
    const float* kp = Kt + (size_t)bidx * 2048;
    for (int l = tid; l < 2048; l += 256) SA[l] = make_float2(qp[l], kp[l]);
    __syncthreads();

    // Forward FFT of z = q + i*k  -> Z in SA
    fft2048_r4(SA, SB, twg, tid, -1.0f);

    // P[f] = Q[f]*conj(K[f]) = 0.25i * (a + conj(b)) * (conj(a) - b)  -> SB
    for (int f = tid; f < 2048; f += 256) {
        float2 a  = SA[f];
        float2 bz = SA[(2048 - f) & 2047];
        float ux = a.x + bz.x, uy = a.y - bz.y;
        float vx = a.x - bz.x, vy = -a.y - bz.y;
        float pr = ux * vx - uy * vy;
        float pi = ux * vy + uy * vx;
        SB[f] = make_float2(-0.25f * pi, 0.25f * pr);
    }
    __syncthreads();

    // Inverse FFT of P -> SB (real part * 1/N is corr)
    fft2048_r4(SB, SA, twg, tid, +1.0f);

    // ---- corr to global + register-resident values for top-k ----
    const float invN = 1.0f / 2048.0f;
    float* cg = corrS + (size_t)bidx * 2048;
    float vals[8];
#pragma unroll
    for (int j = 0; j < 8; j++) {
        const int n = tid + (j << 8);
        const float v = SB[n].x * invN;
        vals[j] = v;
        cg[n] = v;
    }

    // local argmax (index = tid + j*256; ascending j scan keeps lowest index)
    float lmax = vals[0]; int lidx = tid;
#pragma unroll
    for (int j = 1; j < 8; j++) {
        const int ii = tid + (j << 8);
        if (vals[j] > lmax) { lmax = vals[j]; lidx = ii; }
    }

    // ---- top-22: block argmax + knockout, all 256 threads ----
    for (int r = 0; r < TOPK; r++) {
        float bvv = lmax; int bii = lidx;
#pragma unroll
        for (int off = 16; off > 0; off >>= 1) {
            const float ov = __shfl_down_sync(0xffffffffu, bvv, off);
            const int   oi = __shfl_down_sync(0xffffffffu, bii, off);
            if (ov > bvv || (ov == bvv && oi < bii)) { bvv = ov; bii = oi; }
        }
        if (lane == 0) { wv[warp] = bvv; wi[warp] = bii; }
        __syncthreads();
        if (tid < 8) {
            float v2 = wv[tid]; int i2 = wi[tid];
#pragma unroll
            for (int off = 4; off > 0; off >>= 1) {
                const float ov = __shfl_down_sync(0xffu, v2, off);
                const int   oi = __shfl_down_sync(0xffu, i2, off);
                if (ov > v2 || (ov == v2 && oi < i2)) { v2 = ov; i2 = oi; }
            }
            if (tid == 0) { topv[r] = v2; topd[r] = i2; bcast = i2; }
        }
        __syncthreads();
        const int widx = bcast;
        if ((widx & 255) == tid) {
            const int jj = widx >> 8;
#pragma unroll
            for (int j = 0; j < 8; j++) if (j == jj) vals[j] = -1e30f;
            lmax = vals[0]; lidx = tid;
#pragma unroll
            for (int j = 1; j < 8; j++) {
                const int ii = tid + (j << 8);
                if (vals[j] > lmax) { lmax = vals[j]; lidx = ii; }
            }
        }
    }

    // ---- softmax over top-22 + mod-8 aggregation (warp 0) ----
    if (tid < 32) {
        float e = 0.0f;
        const float mx = topv[0];
        if (lane < TOPK) { e = expf(topv[lane] - mx); wts[lane] = e; }
        float ssum = e;
#pragma unroll
        for (int off = 16; off > 0; off >>= 1)
            ssum += __shfl_down_sync(0xffffffffu, ssum, off);
        ssum = __shfl_sync(0xffffffffu, ssum, 0);
        const float inv = 1.0f / ssum;
        if (lane < 8) vsh[lane] = Vs[(size_t)(((b << 3) + lane) << 10) + c];
        __syncwarp();
        if (lane < 8) {
            float acc = 0.0f;
#pragma unroll
            for (int i = 0; i < TOPK; i++)
                acc += wts[i] * vsh[(lane + topd[i]) & 7];
            Rsmall[(size_t)(((b << 3) + lane) << 10) + c] = acc * inv;
        }
    }
}

// ---------------------------------------------------------------------------
// Broadcast: out[b,l,:] = Tout[b*8 + (l%8), :]
// ---------------------------------------------------------------------------
__global__ void broadcast_out(const float* __restrict__ Tout, float* __restrict__ out)
{
    const size_t idx = (size_t)blockIdx.x * 256 + threadIdx.x;  // < ELEMS
    const int cc = (int)(idx & 1023);
    const int l  = (int)((idx >> 10) & 2047);
    const int bb = (int)(idx >> 21);
    out[idx] = Tout[(size_t)(((bb << 3) + (l & 7)) << 10) + cc];
}

// ---------------------------------------------------------------------------
extern "C" void kernel_launch(void* const* d_in, const int* in_sizes, int n_in,
                              void* d_out, int out_size)
{
    (void)in_sizes; (void)n_in; (void)out_size;
    const float* queries = (const float*)d_in[0];
    const float* keys    = (const float*)d_in[1];
    const float* values  = (const float*)d_in[2];
    const float* Wq = (const float*)d_in[3];
    const float* bq = (const float*)d_in[4];
    const float* Wk = (const float*)d_in[5];
    const float* bk = (const float*)d_in[6];
    const float* Wv = (const float*)d_in[7];
    const float* bv = (const float*)d_in[8];
    const float* Wo = (const float*)d_in[9];
    const float* bo = (const float*)d_in[10];
    float* out = (float*)d_out;

    float *Qt, *Kt, *corrS, *Vs, *Rs, *To;
    __nv_bfloat16 *Xhi, *Xlo, *Whi, *Wlo;
    float2* twp;
    cudaGetSymbolAddress((void**)&Qt, g_Qt);
    cudaGetSymbolAddress((void**)&Kt, g_Kt);
    cudaGetSymbolAddress((void**)&corrS, g_corr);
    cudaGetSymbolAddress((void**)&Vs, g_Vs);
    cudaGetSymbolAddress((void**)&Rs, g_Rs);
    cudaGetSymbolAddress((void**)&To, g_To);
    cudaGetSymbolAddress((void**)&Xhi, g_Xhi);
    cudaGetSymbolAddress((void**)&Xlo, g_Xlo);
    cudaGetSymbolAddress((void**)&Whi, g_Whi);
    cudaGetSymbolAddress((void**)&Wlo, g_Wlo);
    cudaGetSymbolAddress((void**)&twp, g_tw);

    static int attr_done = 0;
    if (!attr_done) {
        cudaFuncSetAttribute(gemm_bf16x2_t,
                             cudaFuncAttributeMaxDynamicSharedMemorySize, GEMM_DSMEM);
        attr_done = 1;
    }

    fill_tw<<<4, 256>>>(twp);

    dim3 gemmGrid(1024 / 128, (BATCH * SEQ) / 128);  // (8, 128)

    // Q projection on tensor cores (split-bf16, 3 products), writes Qt directly
    split_bf16<<<ELEMS / 1024, 256>>>(queries, Xhi, Xlo);
    split_bf16<<<(DIM * DIM) / 1024, 256>>>(Wq, Whi, Wlo);
    gemm_bf16x2_t<<<gemmGrid, 256, GEMM_DSMEM>>>(Xhi, Xlo, Whi, Wlo, bq, Qt);

    // K projection, writes Kt directly
    split_bf16<<<ELEMS / 1024, 256>>>(keys, Xhi, Xlo);
    split_bf16<<<(DIM * DIM) / 1024, 256>>>(Wk, Whi, Wlo);
    gemm_bf16x2_t<<<gemmGrid, 256, GEMM_DSMEM>>>(Xhi, Xlo, Whi, Wlo, bk, Kt);

    // V projection: only rows l = 0..7 per batch matter (mod-8 quirk)
    rowgemm64<<<64, 256>>>(values, Wv, bv, Vs, (size_t)SEQ * DIM);

    // FFT correlation + top-k + mod-8 aggregation
    fft_corr_topk<<<BATCH * DIM, 256>>>(Qt, Kt, Vs, twp, corrS, Rs);

    // corr [B,C,L] -> second output half [B,L,C]
    transpose_bRC<<<dim3(2048 / 32, 1024 / 32, BATCH), dim3(32, 8)>>>(corrS, out + (size_t)ELEMS, 1024, 2048);

    // out = result @ Wo + bo  (result rows periodic: 64 distinct rows)
    rowgemm64<<<64, 256>>>(Rs, Wo, bo, To, (size_t)8 * DIM);
    broadcast_out<<<ELEMS / 256, 256>>>(To, out);
}

// round 9
// speedup vs baseline: 2.6490x; 1.0573x over previous
#include <cuda_runtime.h>
#include <cuda_bf16.h>
#include <cstdint>
#include <cmath>

// ---------------------------------------------------------------------------
// Problem constants: B=8, L=2048, D=1024 (H=16, E=64 -> C = 1024), topk=22
// ---------------------------------------------------------------------------
#define BATCH 8
#define SEQ   2048
#define DIM   1024
#define TOPK  22
#define ELEMS (BATCH * SEQ * DIM)   // 16777216

// Scratch (allocation-free: __device__ globals)
__device__ float g_Qt[ELEMS];     // Q projected+transposed [B,C,L]
__device__ float g_Kt[ELEMS];     // K projected+transposed [B,C,L]
__device__ float g_corr[ELEMS];   // corr [B,C,L]
__device__ float g_Vs[BATCH * 8 * DIM];  // V rows l=0..7 only
__device__ float g_Rs[BATCH * 8 * DIM];  // aggregated result (periodic rows)
__device__ float g_To[BATCH * 8 * DIM];  // Rs @ Wo + bo
__device__ __nv_bfloat16 g_Xhi[ELEMS];   // split-bf16 staging for activations
__device__ __nv_bfloat16 g_Xlo[ELEMS];
__device__ __nv_bfloat16 g_Whi[DIM * DIM];
__device__ __nv_bfloat16 g_Wlo[DIM * DIM];
__device__ float2 g_tw[1024];            // FFT twiddles exp(+i 2 pi e / 2048)

// ---------------------------------------------------------------------------
// Split fp32 -> (hi, lo) bf16 pair.  x ~= hi + lo with ~17-bit mantissa.
// ---------------------------------------------------------------------------
__global__ void split_bf16(const float* __restrict__ x,
                           __nv_bfloat16* __restrict__ hi,
                           __nv_bfloat16* __restrict__ lo)
{
    const int i = blockIdx.x * 256 + threadIdx.x;  // one float4 per thread
    float4 v = ((const float4*)x)[i];
    float vv[4] = {v.x, v.y, v.z, v.w};
    __nv_bfloat16 h[4], l[4];
#pragma unroll
    for (int j = 0; j < 4; j++) {
        h[j] = __float2bfloat16(vv[j]);
        l[j] = __float2bfloat16(vv[j] - __bfloat162float(h[j]));
    }
    *(uint2*)(hi + 4 * (size_t)i) = *(uint2*)h;
    *(uint2*)(lo + 4 * (size_t)i) = *(uint2*)l;
}

// ---------------------------------------------------------------------------
// Tensor-core GEMM with fused transposed output:
//   T[b, n, l] = (X @ W + bias)[b*2048 + l, n]
// 3-stage cp.async pipeline, k-step 32, one __syncthreads per k-iter,
// 8 warps (2x4), block tile 128x128, bf16 hi/lo split (3 mma products).
// ---------------------------------------------------------------------------
#define APAD 40    // A smem row halves (32 data + 8 pad) -> 80B rows (16B mult)
#define BPAD 136   // B smem row halves (128 data + 8 pad) -> 272B rows
#define A_BYTES (128 * APAD * 2)          // 10240
#define B_BYTES (32 * BPAD * 2)           // 8704
#define STAGE_BYTES (2 * A_BYTES + 2 * B_BYTES)  // 37888
#define GEMM_DSMEM (3 * STAGE_BYTES)             // 113664

__device__ __forceinline__ void cp16(uint32_t d, const void* s) {
    asm volatile("cp.async.cg.shared.global [%0], [%1], 16;\n" :: "r"(d), "l"(s));
}
__device__ __forceinline__ void cp_commit() { asm volatile("cp.async.commit_group;\n"); }
__device__ __forceinline__ void cp_wait0()  { asm volatile("cp.async.wait_group 0;\n"); }
__device__ __forceinline__ void cp_wait1()  { asm volatile("cp.async.wait_group 1;\n"); }

__device__ __forceinline__ void ldsm4(uint32_t* r, uint32_t a) {
    asm volatile("ldmatrix.sync.aligned.m8n8.x4.shared.b16 {%0,%1,%2,%3},[%4];"
                 : "=r"(r[0]), "=r"(r[1]), "=r"(r[2]), "=r"(r[3]) : "r"(a));
}
__device__ __forceinline__ void ldsm4t(uint32_t* r, uint32_t a) {
    asm volatile("ldmatrix.sync.aligned.m8n8.x4.trans.shared.b16 {%0,%1,%2,%3},[%4];"
                 : "=r"(r[0]), "=r"(r[1]), "=r"(r[2]), "=r"(r[3]) : "r"(a));
}
__device__ __forceinline__ void mma_bf16(float* c, const uint32_t* a, const uint32_t* b) {
    asm volatile("mma.sync.aligned.m16n8k16.row.col.f32.bf16.bf16.f32 "
                 "{%0,%1,%2,%3},{%4,%5,%6,%7},{%8,%9},{%0,%1,%2,%3};"
                 : "+f"(c[0]), "+f"(c[1]), "+f"(c[2]), "+f"(c[3])
                 : "r"(a[0]), "r"(a[1]), "r"(a[2]), "r"(a[3]), "r"(b[0]), "r"(b[1]));
}

__global__ __launch_bounds__(256) void gemm_bf16x2_t(
    const __nv_bfloat16* __restrict__ Ahi, const __nv_bfloat16* __restrict__ Alo,
    const __nv_bfloat16* __restrict__ Bhi, const __nv_bfloat16* __restrict__ Blo,
    const float* __restrict__ bias, float* __restrict__ T)
{
    extern __shared__ __align__(16) char dsm[];

    const int tid = threadIdx.x;
    const int warp = tid >> 5, lane = tid & 31;
    const int wm = warp >> 2, wn = warp & 3;          // 2 x 4 warp grid
    const int m0 = blockIdx.y * 128, n0 = blockIdx.x * 128;

    float acc[4][4][4];
#pragma unroll
    for (int i = 0; i < 4; i++)
#pragma unroll
        for (int j = 0; j < 4; j++)
#pragma unroll
            for (int k = 0; k < 4; k++) acc[i][j][k] = 0.0f;

#define SAH(s) ((__nv_bfloat16*)(dsm + (s) * STAGE_BYTES))
#define SAL(s) ((__nv_bfloat16*)(dsm + (s) * STAGE_BYTES + A_BYTES))
#define SBH(s) ((__nv_bfloat16*)(dsm + (s) * STAGE_BYTES + 2 * A_BYTES))
#define SBL(s) ((__nv_bfloat16*)(dsm + (s) * STAGE_BYTES + 2 * A_BYTES + B_BYTES))

    // A: 128 rows x 4 16B-chunks (32 halves); B: 32 rows x 16 16B-chunks
#define GEMM_ISSUE(s, k0)                                                              \
    do {                                                                               \
        _Pragma("unroll")                                                              \
        for (int t = 0; t < 2; t++) {                                                  \
            const int id = tid + t * 256;                                              \
            const int arow = id >> 2, ac4 = id & 3;                                    \
            cp16((uint32_t)__cvta_generic_to_shared(SAH(s) + arow * APAD + ac4 * 8),   \
                 Ahi + (size_t)(m0 + arow) * 1024 + (k0) + ac4 * 8);                   \
            cp16((uint32_t)__cvta_generic_to_shared(SAL(s) + arow * APAD + ac4 * 8),   \
                 Alo + (size_t)(m0 + arow) * 1024 + (k0) + ac4 * 8);                   \
            const int brow = id >> 4, bc = id & 15;                                    \
            cp16((uint32_t)__cvta_generic_to_shared(SBH(s) + brow * BPAD + bc * 8),    \
                 Bhi + (size_t)((k0) + brow) * 1024 + n0 + bc * 8);                    \
            cp16((uint32_t)__cvta_generic_to_shared(SBL(s) + brow * BPAD + bc * 8),    \
                 Blo + (size_t)((k0) + brow) * 1024 + n0 + bc * 8);                    \
        }                                                                              \
        cp_commit();                                                                   \
    } while (0)

    GEMM_ISSUE(0, 0);
    GEMM_ISSUE(1, 32);

    const int ar = lane & 15, ac8 = (lane >> 4) * 8;    // ldmatrix lane addressing

    for (int it = 0; it < 32; it++) {
        if (it == 31) cp_wait0(); else cp_wait1();
        __syncthreads();

        const int s = it % 3;
#pragma unroll
        for (int kk = 0; kk < 32; kk += 16) {
            uint32_t ah[4][4], al[4][4], bh[4][2], bl[4][2];
#pragma unroll
            for (int mb = 0; mb < 4; mb++) {
                const int row = wm * 64 + mb * 16 + ar;
                ldsm4(ah[mb], (uint32_t)__cvta_generic_to_shared(SAH(s) + row * APAD + kk + ac8));
                ldsm4(al[mb], (uint32_t)__cvta_generic_to_shared(SAL(s) + row * APAD + kk + ac8));
            }
#pragma unroll
            for (int nb2 = 0; nb2 < 2; nb2++) {
                uint32_t r[4];
                const int col = wn * 32 + nb2 * 16 + ac8;
                ldsm4t(r, (uint32_t)__cvta_generic_to_shared(SBH(s) + (kk + ar) * BPAD + col));
                bh[nb2 * 2][0] = r[0]; bh[nb2 * 2][1] = r[1];
                bh[nb2 * 2 + 1][0] = r[2]; bh[nb2 * 2 + 1][1] = r[3];
                ldsm4t(r, (uint32_t)__cvta_generic_to_shared(SBL(s) + (kk + ar) * BPAD + col));
                bl[nb2 * 2][0] = r[0]; bl[nb2 * 2][1] = r[1];
                bl[nb2 * 2 + 1][0] = r[2]; bl[nb2 * 2 + 1][1] = r[3];
            }
#pragma unroll
            for (int mb = 0; mb < 4; mb++)
#pragma unroll
                for (int nb = 0; nb < 4; nb++) {
                    mma_bf16(acc[mb][nb], ah[mb], bh[nb]);   // hi*hi
                    mma_bf16(acc[mb][nb], ah[mb], bl[nb]);   // hi*lo
                    mma_bf16(acc[mb][nb], al[mb], bh[nb]);   // lo*hi
                }
        }
        if (it + 2 < 32) GEMM_ISSUE((it + 2) % 3, (it + 2) * 32);
    }

    // ---- Fused transposed epilogue: write T[b, c, l] (coalesced along l) ----
    float* sT = (float*)dsm;                 // 64 * 132 * 4 = 33792 B (fits)
    const int g = lane >> 2, t2 = (lane & 3) * 2;
    const int l0 = m0 & 2047;
    const int bq = m0 >> 11;

#pragma unroll
    for (int p = 0; p < 2; p++) {
        __syncthreads();
        if ((wn >> 1) == p) {
            const int chalf = (wn & 1) * 32;
#pragma unroll
            for (int mb = 0; mb < 4; mb++) {
                const int row = wm * 64 + mb * 16 + g;
#pragma unroll
                for (int nb = 0; nb < 4; nb++) {
                    const int cl = chalf + nb * 8 + t2;
                    const int cgl = n0 + p * 64 + cl;
                    const float b0 = bias[cgl], b1 = bias[cgl + 1];
                    sT[cl * 132 + row]           = acc[mb][nb][0] + b0;
                    sT[(cl + 1) * 132 + row]     = acc[mb][nb][1] + b1;
                    sT[cl * 132 + row + 8]       = acc[mb][nb][2] + b0;
                    sT[(cl + 1) * 132 + row + 8] = acc[mb][nb][3] + b1;
                }
            }
        }
        __syncthreads();
        const size_t cb = (size_t)bq * 1024 + n0 + p * 64;
#pragma unroll
        for (int i = tid; i < 2048; i += 256) {     // 64 c x 32 float4
            const int c = i >> 5, m4 = (i & 31) << 2;
            float4 v = *(float4*)&sT[c * 132 + m4];
            *(float4*)&T[((cb + c) << 11) + l0 + m4] = v;
        }
    }
}

// ---------------------------------------------------------------------------
// Small GEMM, coalesced: Y[64,1024] = X[64,1024] @ W + bias.
// Row r of X maps to X + (r/8)*b_stride + (r%8)*1024.
// ---------------------------------------------------------------------------
__global__ __launch_bounds__(256) void rowgemm64(
    const float* __restrict__ X, const float* __restrict__ W,
    const float* __restrict__ bias, float* __restrict__ Y, size_t b_stride)
{
    __shared__ float Xs[64][128];     // 32 KB
    __shared__ float Ws[16][129];

    const int tid = threadIdx.x;
    const int n0 = blockIdx.x * 16;
    const int n = tid & 15, rg = tid >> 4;   // 16 row-groups x 4 rows

    float a0 = 0.f, a1 = 0.f, a2 = 0.f, a3 = 0.f;

    for (int kt = 0; kt < 8; kt++) {
#pragma unroll
        for (int j = 0; j < 8; j++) {                 // X tile: 2048 float4
            const int i = tid + j * 256;
            const int row = i >> 5, c4 = (i & 31) << 2;
            const float* xr = X + (size_t)(row >> 3) * b_stride + (size_t)(row & 7) * 1024;
            *(float4*)&Xs[row][c4] = *(const float4*)(xr + kt * 128 + c4);
        }
#pragma unroll
        for (int j = 0; j < 8; j++) {                 // W tile: 128k x 16n -> Ws[n][k]
            const int i = tid + j * 256;
            const int k = i >> 4, nn = i & 15;
            Ws[nn][k] = W[(size_t)(kt * 128 + k) * 1024 + n0 + nn];
        }
        __syncthreads();
#pragma unroll 4
        for (int k = 0; k < 128; k++) {
            const float w = Ws[n][k];
            a0 += Xs[rg * 4 + 0][k] * w;
            a1 += Xs[rg * 4 + 1][k] * w;
            a2 += Xs[rg * 4 + 2][k] * w;
            a3 += Xs[rg * 4 + 3][k] * w;
        }
        __syncthreads();
    }
    const float bb = bias[n0 + n];
    Y[(size_t)(rg * 4 + 0) * 1024 + n0 + n] = a0 + bb;
    Y[(size_t)(rg * 4 + 1) * 1024 + n0 + n] = a1 + bb;
    Y[(size_t)(rg * 4 + 2) * 1024 + n0 + n] = a2 + bb;
    Y[(size_t)(rg * 4 + 3) * 1024 + n0 + n] = a3 + bb;
}

// ---------------------------------------------------------------------------
// Batched 2D transpose: out[b, j, i] = in[b, i, j], i<R, j<C (R,C mult of 32)
// ---------------------------------------------------------------------------
__global__ void transpose_bRC(const float* __restrict__ in, float* __restrict__ out,
                              int R, int C)
{
    __shared__ float tile[32][33];
    const int bz = blockIdx.z;
    const float* ip = in + (size_t)bz * R * C;
    float* op = out + (size_t)bz * R * C;
    const int j0 = blockIdx.x * 32;
    const int i0 = blockIdx.y * 32;
    const int tx = threadIdx.x, ty = threadIdx.y;
#pragma unroll
    for (int k = 0; k < 4; k++)
        tile[ty + k * 8][tx] = ip[(size_t)(i0 + ty + k * 8) * C + (j0 + tx)];
    __syncthreads();
#pragma unroll
    for (int k = 0; k < 4; k++)
        op[(size_t)(j0 + ty + k * 8) * R + (i0 + tx)] = tile[tx][ty + k * 8];
}

// ---------------------------------------------------------------------------
// FFT twiddle table: g_tw[e] = (cos, sin)(2 pi e / 2048), e < 1024
// ---------------------------------------------------------------------------
__global__ void fill_tw(float2* tw)
{
    const int i = blockIdx.x * 256 + threadIdx.x;
    if (i < 1024) {
        float s, c;
        sincosf(6.28318530717958647692f * (float)i / 2048.0f, &s, &c);
        tw[i] = make_float2(c, s);
    }
}

// ---------------------------------------------------------------------------
// Register-resident mixed-radix FFT, N=2048 = 16 * 16 * 8, 128 threads.
// Stockham: y_m = DFT_R(x)_m * w2048^{m*p*s}, outputs at q + R*s*p + m*s.
// Twiddle: w2048^e with tw[e<1024]; e in [1024,2048) -> negate.
// ---------------------------------------------------------------------------
#define PD(i) ((i) + ((i) >> 4))          // padded smem index (float2 units)
#define FFT_SSZ 2176                       // PD(2047)+1 = 2174 -> round up

__device__ __forceinline__ float2 cmul(float2 a, float2 b) {
    return make_float2(a.x * b.x - a.y * b.y, a.x * b.y + a.y * b.x);
}
__device__ __forceinline__ float2 twget(const float2* tw, int e, float sign) {
    float2 t = __ldg(&tw[e & 1023]);
    const float fl = (e & 1024) ? -1.0f : 1.0f;
    return make_float2(fl * t.x, fl * sign * t.y);
}
__device__ __forceinline__ void dft4(float2& x0, float2& x1, float2& x2, float2& x3,
                                     float sign) {
    const float apcx = x0.x + x2.x, apcy = x0.y + x2.y;
    const float amcx = x0.x - x2.x, amcy = x0.y - x2.y;
    const float bpdx = x1.x + x3.x, bpdy = x1.y + x3.y;
    const float bmdx = x1.x - x3.x, bmdy = x1.y - x3.y;
    x0 = make_float2(apcx + bpdx, apcy + bpdy);
    x1 = make_float2(amcx - sign * bmdy, amcy + sign * bmdx);
    x2 = make_float2(apcx - bpdx, apcy - bpdy);
    x3 = make_float2(amcx + sign * bmdy, amcy - sign * bmdx);
}
// In-place DFT16; output X_{(s>>2)+4*(s&3)} lands in slot s.
__device__ __forceinline__ void dft16(float2* x, const float2* tw, float sign) {
#pragma unroll
    for (int j1 = 0; j1 < 4; j1++)
        dft4(x[j1], x[j1 + 4], x[j1 + 8], x[j1 + 12], sign);
#pragma unroll
    for (int j1 = 1; j1 < 4; j1++)
#pragma unroll
        for (int k2 = 1; k2 < 4; k2++)
            x[j1 + 4 * k2] = cmul(x[j1 + 4 * k2], twget(tw, 128 * j1 * k2, sign));
#pragma unroll
    for (int k2 = 0; k2 < 4; k2++)
        dft4(x[4 * k2], x[1 + 4 * k2], x[2 + 4 * k2], x[3 + 4 * k2], sign);
}
// In-place DFT8, natural-order output in x[0..7].
__device__ __forceinline__ void dft8(float2* x, float sign) {
    const float s2 = 0.70710678118654752440f;
    float2 e[4], o[4];
#pragma unroll
    for (int j = 0; j < 4; j++) {
        e[j] = make_float2(x[j].x + x[j + 4].x, x[j].y + x[j + 4].y);
        o[j] = make_float2(x[j].x - x[j + 4].x, x[j].y - x[j + 4].y);
    }
    o[1] = cmul(o[1], make_float2(s2, sign * s2));
    o[2] = make_float2(-sign * o[2].y, sign * o[2].x);
    o[3] = cmul(o[3], make_float2(-s2, sign * s2));
    dft4(e[0], e[1], e[2], e[3], sign);
    dft4(o[0], o[1], o[2], o[3], sign);
#pragma unroll
    for (int k = 0; k < 4; k++) { x[2 * k] = e[k]; x[2 * k + 1] = o[k]; }
}

// x[m] = in[tid + 128m] on entry. Result (natural order) lands in Sa[PD(n)].
__device__ __forceinline__ void fft2048_reg(float2* x, float2* Sa, float2* Sb,
                                            const float2* tw, int tid, float sign)
{
    // Stage A: radix-16, s=1, p=tid, q=0
    dft16(x, tw, sign);
#pragma unroll
    for (int s = 0; s < 16; s++) {
        const int m = (s >> 2) | ((s & 3) << 2);
        Sa[PD(16 * tid + m)] = cmul(x[s], twget(tw, m * tid, sign));
    }
    __syncthreads();
    // Stage B: radix-16, s=16, q=tid&15, p=tid>>4
    {
        const int q = tid & 15, p = tid >> 4;
#pragma unroll
        for (int m = 0; m < 16; m++) x[m] = Sa[PD(q + 16 * p + 128 * m)];
        dft16(x, tw, sign);
        const int e = 16 * p;
        const int ob = q + 256 * p;
#pragma unroll
        for (int s = 0; s < 16; s++) {
            const int m = (s >> 2) | ((s & 3) << 2);
            Sb[PD(ob + 16 * m)] = cmul(x[s], twget(tw, m * e, sign));
        }
    }
    __syncthreads();
    // Stage C: radix-8, s=256, p=0 (twiddle-free), 2 butterflies/thread
#pragma unroll
    for (int h = 0; h < 2; h++) {
        const int q = tid + 128 * h;
        float2 y[8];
#pragma unroll
        for (int m = 0; m < 8; m++) y[m] = Sb[PD(q + 256 * m)];
        dft8(y, sign);
#pragma unroll
        for (int m = 0; m < 8; m++) Sa[PD(q + 256 * m)] = y[m];
    }
    __syncthreads();
}

// ---------------------------------------------------------------------------
// Per-(b,c) kernel: packed register-FFT correlation -> corr, then parallel
// top-22 + softmax + mod-8 V aggregation.  128 threads.
// ---------------------------------------------------------------------------
__global__ __launch_bounds__(128) void fft_corr_topk(
    const float* __restrict__ Qt, const float* __restrict__ Kt,
    const float* __restrict__ Vs, const float2* __restrict__ twg,
    float* __restrict__ corrS, float* __restrict__ Rsmall)
{
    __shared__ float2 S1[FFT_SSZ];
    __shared__ float2 S2[FFT_SSZ];
    __shared__ float topv[TOPK];
    __shared__ int   topd[TOPK];
    __shared__ float wts[TOPK];
    __shared__ float vsh[8];
    __shared__ float wv[4];
    __shared__ int   wi[4];
    __shared__ int   bcast;

    const int tid = threadIdx.x;
    const int lane = tid & 31, warp = tid >> 5;
    const int bidx = blockIdx.x;              // b*1024 + c
    const int b = bidx >> 10;
    const int c = bidx & 1023;

    const float* qp = Qt + (size_t)bidx * 2048;
    const float* kp = Kt + (size_t)bidx * 2048;

    float2 x[16];
    // Forward FFT of z = q + i*k (load gmem -> regs), result -> S1
#pragma unroll
    for (int m = 0; m < 16; m++) {
        const int n = tid + (m << 7);
        x[m] = make_float2(qp[n], kp[n]);
    }
    fft2048_reg(x, S1, S2, twg, tid, -1.0f);

    // P[f] = Q[f]*conj(K[f]) = 0.25i * (a + conj(b)) * (conj(a) - b)  -> S2
#pragma unroll
    for (int m = 0; m < 16; m++) {
        const int f = tid + (m << 7);
        float2 a  = S1[PD(f)];
        float2 bz = S1[PD((2048 - f) & 2047)];
        float ux = a.x + bz.x, uy = a.y - bz.y;
        float vx = a.x - bz.x, vy = -a.y - bz.y;
        float pr = ux * vx - uy * vy;
        float pi = ux * vy + uy * vx;
        S2[PD(f)] = make_float2(-0.25f * pi, 0.25f * pr);
    }
    __syncthreads();

    // Inverse FFT of P (load S2 -> regs), result -> S1
#pragma unroll
    for (int m = 0; m < 16; m++) x[m] = S2[PD(tid + (m << 7))];
    fft2048_reg(x, S1, S2, twg, tid, +1.0f);

    // ---- corr to global + register-resident values for top-k ----
    const float invN = 1.0f / 2048.0f;
    float* cg = corrS + (size_t)bidx * 2048;
    float vals[16];
#pragma unroll
    for (int m = 0; m < 16; m++) {
        const int n = tid + (m << 7);
        const float v = S1[PD(n)].x * invN;
        vals[m] = v;
        cg[n] = v;
    }

    // local argmax (ascending m scan => lowest index kept on ties)
    float lmax = vals[0]; int lidx = tid;
#pragma unroll
    for (int m = 1; m < 16; m++) {
        const int ii = tid + (m << 7);
        if (vals[m] > lmax) { lmax = vals[m]; lidx = ii; }
    }

    // ---- top-22: block argmax + knockout ----
    for (int r = 0; r < TOPK; r++) {
        float bvv = lmax; int bii = lidx;
#pragma unroll
        for (int off = 16; off > 0; off >>= 1) {
            const float ov = __shfl_down_sync(0xffffffffu, bvv, off);
            const int   oi = __shfl_down_sync(0xffffffffu, bii, off);
            if (ov > bvv || (ov == bvv && oi < bii)) { bvv = ov; bii = oi; }
        }
        if (lane == 0) { wv[warp] = bvv; wi[warp] = bii; }
        __syncthreads();
        if (tid == 0) {
            float v2 = wv[0]; int i2 = wi[0];
#pragma unroll
            for (int w = 1; w < 4; w++) {
                if (wv[w] > v2 || (wv[w] == v2 && wi[w] < i2)) { v2 = wv[w]; i2 = wi[w]; }
            }
            topv[r] = v2; topd[r] = i2; bcast = i2;
        }
        __syncthreads();
        const int widx = bcast;
        if ((widx & 127) == tid) {
            const int jj = widx >> 7;
#pragma unroll
            for (int m = 0; m < 16; m++) if (m == jj) vals[m] = -1e30f;
            lmax = vals[0]; lidx = tid;
#pragma unroll
            for (int m = 1; m < 16; m++) {
                const int ii = tid + (m << 7);
                if (vals[m] > lmax) { lmax = vals[m]; lidx = ii; }
            }
        }
    }

    // ---- softmax over top-22 + mod-8 aggregation (warp 0) ----
    if (tid < 32) {
        float e = 0.0f;
        const float mx = topv[0];
        if (lane < TOPK) { e = expf(topv[lane] - mx); wts[lane] = e; }
        float ssum = e;
#pragma unroll
        for (int off = 16; off > 0; off >>= 1)
            ssum += __shfl_down_sync(0xffffffffu, ssum, off);
        ssum = __shfl_sync(0xffffffffu, ssum, 0);
        const float inv = 1.0f / ssum;
        if (lane < 8) vsh[lane] = Vs[(size_t)(((b << 3) + lane) << 10) + c];
        __syncwarp();
        if (lane < 8) {
            float acc = 0.0f;
#pragma unroll
            for (int i = 0; i < TOPK; i++)
                acc += wts[i] * vsh[(lane + topd[i]) & 7];
            Rsmall[(size_t)(((b << 3) + lane) << 10) + c] = acc * inv;
        }
    }
}

// ---------------------------------------------------------------------------
// Broadcast: out[b,l,:] = Tout[b*8 + (l%8), :]
// ---------------------------------------------------------------------------
__global__ void broadcast_out(const float* __restrict__ Tout, float* __restrict__ out)
{
    const size_t idx = (size_t)blockIdx.x * 256 + threadIdx.x;  // < ELEMS
    const int cc = (int)(idx & 1023);
    const int l  = (int)((idx >> 10) & 2047);
    const int bb = (int)(idx >> 21);
    out[idx] = Tout[(size_t)(((bb << 3) + (l & 7)) << 10) + cc];
}

// ---------------------------------------------------------------------------
extern "C" void kernel_launch(void* const* d_in, const int* in_sizes, int n_in,
                              void* d_out, int out_size)
{
    (void)in_sizes; (void)n_in; (void)out_size;
    const float* queries = (const float*)d_in[0];
    const float* keys    = (const float*)d_in[1];
    const float* values  = (const float*)d_in[2];
    const float* Wq = (const float*)d_in[3];
    const float* bq = (const float*)d_in[4];
    const float* Wk = (const float*)d_in[5];
    const float* bk = (const float*)d_in[6];
    const float* Wv = (const float*)d_in[7];
    const float* bv = (const float*)d_in[8];
    const float* Wo = (const float*)d_in[9];
    const float* bo = (const float*)d_in[10];
    float* out = (float*)d_out;

    float *Qt, *Kt, *corrS, *Vs, *Rs, *To;
    __nv_bfloat16 *Xhi, *Xlo, *Whi, *Wlo;
    float2* twp;
    cudaGetSymbolAddress((void**)&Qt, g_Qt);
    cudaGetSymbolAddress((void**)&Kt, g_Kt);
    cudaGetSymbolAddress((void**)&corrS, g_corr);
    cudaGetSymbolAddress((void**)&Vs, g_Vs);
    cudaGetSymbolAddress((void**)&Rs, g_Rs);
    cudaGetSymbolAddress((void**)&To, g_To);
    cudaGetSymbolAddress((void**)&Xhi, g_Xhi);
    cudaGetSymbolAddress((void**)&Xlo, g_Xlo);
    cudaGetSymbolAddress((void**)&Whi, g_Whi);
    cudaGetSymbolAddress((void**)&Wlo, g_Wlo);
    cudaGetSymbolAddress((void**)&twp, g_tw);

    static int attr_done = 0;
    if (!attr_done) {
        cudaFuncSetAttribute(gemm_bf16x2_t,
                             cudaFuncAttributeMaxDynamicSharedMemorySize, GEMM_DSMEM);
        attr_done = 1;
    }

    fill_tw<<<4, 256>>>(twp);

    dim3 gemmGrid(1024 / 128, (BATCH * SEQ) / 128);  // (8, 128)

    // Q projection on tensor cores (split-bf16, 3 products), writes Qt directly
    split_bf16<<<ELEMS / 1024, 256>>>(queries, Xhi, Xlo);
    split_bf16<<<(DIM * DIM) / 1024, 256>>>(Wq, Whi, Wlo);
    gemm_bf16x2_t<<<gemmGrid, 256, GEMM_DSMEM>>>(Xhi, Xlo, Whi, Wlo, bq, Qt);

    // K projection, writes Kt directly
    split_bf16<<<ELEMS / 1024, 256>>>(keys, Xhi, Xlo);
    split_bf16<<<(DIM * DIM) / 1024, 256>>>(Wk, Whi, Wlo);
    gemm_bf16x2_t<<<gemmGrid, 256, GEMM_DSMEM>>>(Xhi, Xlo, Whi, Wlo, bk, Kt);

    // V projection: only rows l = 0..7 per batch matter (mod-8 quirk)
    rowgemm64<<<64, 256>>>(values, Wv, bv, Vs, (size_t)SEQ * DIM);

    // FFT correlation + top-k + mod-8 aggregation
    fft_corr_topk<<<BATCH * DIM, 128>>>(Qt, Kt, Vs, twp, corrS, Rs);

    // corr [B,C,L] -> second output half [B,L,C]
    transpose_bRC<<<dim3(2048 / 32, 1024 / 32, BATCH), dim3(32, 8)>>>(corrS, out + (size_t)ELEMS, 1024, 2048);

    // out = result @ Wo + bo  (result rows periodic: 64 distinct rows)
    rowgemm64<<<64, 256>>>(Rs, Wo, bo, To, (size_t)8 * DIM);
    broadcast_out<<<ELEMS / 256, 256>>>(To, out);
}

// round 10
// speedup vs baseline: 2.8757x; 1.0856x over previous
#include <cuda_runtime.h>
#include <cuda_bf16.h>
#include <cstdint>
#include <cmath>

// ---------------------------------------------------------------------------
// Problem constants: B=8, L=2048, D=1024 (H=16, E=64 -> C = 1024), topk=22
// ---------------------------------------------------------------------------
#define BATCH 8
#define SEQ   2048
#define DIM   1024
#define TOPK  22
#define ELEMS (BATCH * SEQ * DIM)   // 16777216

// Scratch (allocation-free: __device__ globals)
__device__ float g_Qt[ELEMS];     // Q projected+transposed [B,C,L]
__device__ float g_Kt[ELEMS];     // K projected+transposed [B,C,L]
__device__ float g_corr[ELEMS];   // corr [B,C,L]
__device__ float g_Vs[BATCH * 8 * DIM];  // V rows l=0..7 only
__device__ float g_Rs[BATCH * 8 * DIM];  // aggregated result (periodic rows)
__device__ float g_To[BATCH * 8 * DIM];  // Rs @ Wo + bo
__device__ __nv_bfloat16 g_Xhi[ELEMS];   // split-bf16 staging for activations
__device__ __nv_bfloat16 g_Xlo[ELEMS];
__device__ __nv_bfloat16 g_Whi[DIM * DIM];
__device__ __nv_bfloat16 g_Wlo[DIM * DIM];
__device__ float2 g_tw[1024];            // FFT twiddles exp(+i 2 pi e / 2048)

// ---------------------------------------------------------------------------
// Split fp32 -> (hi, lo) bf16 pair.  x ~= hi + lo with ~17-bit mantissa.
// ---------------------------------------------------------------------------
__global__ void split_bf16(const float* __restrict__ x,
                           __nv_bfloat16* __restrict__ hi,
                           __nv_bfloat16* __restrict__ lo)
{
    const int i = blockIdx.x * 256 + threadIdx.x;  // one float4 per thread
    float4 v = ((const float4*)x)[i];
    float vv[4] = {v.x, v.y, v.z, v.w};
    __nv_bfloat16 h[4], l[4];
#pragma unroll
    for (int j = 0; j < 4; j++) {
        h[j] = __float2bfloat16(vv[j]);
        l[j] = __float2bfloat16(vv[j] - __bfloat162float(h[j]));
    }
    *(uint2*)(hi + 4 * (size_t)i) = *(uint2*)h;
    *(uint2*)(lo + 4 * (size_t)i) = *(uint2*)l;
}

// ---------------------------------------------------------------------------
// Tensor-core GEMM with fused transposed output:
//   T[b, n, l] = (X @ W + bias)[b*2048 + l, n]
// 3-stage cp.async pipeline, k-step 32, one __syncthreads per k-iter,
// 8 warps (2x4), block tile 128x128, bf16 hi/lo split (3 mma products,
// product-outermost issue order to hide accumulator RAW).
// ---------------------------------------------------------------------------
#define APAD 40    // A smem row halves (32 data + 8 pad) -> 80B rows (16B mult)
#define BPAD 136   // B smem row halves (128 data + 8 pad) -> 272B rows
#define A_BYTES (128 * APAD * 2)          // 10240
#define B_BYTES (32 * BPAD * 2)           // 8704
#define STAGE_BYTES (2 * A_BYTES + 2 * B_BYTES)  // 37888
#define GEMM_DSMEM (3 * STAGE_BYTES)             // 113664

__device__ __forceinline__ void cp16(uint32_t d, const void* s) {
    asm volatile("cp.async.cg.shared.global [%0], [%1], 16;\n" :: "r"(d), "l"(s));
}
__device__ __forceinline__ void cp_commit() { asm volatile("cp.async.commit_group;\n"); }
__device__ __forceinline__ void cp_wait0()  { asm volatile("cp.async.wait_group 0;\n"); }
__device__ __forceinline__ void cp_wait1()  { asm volatile("cp.async.wait_group 1;\n"); }

__device__ __forceinline__ void ldsm4(uint32_t* r, uint32_t a) {
    asm volatile("ldmatrix.sync.aligned.m8n8.x4.shared.b16 {%0,%1,%2,%3},[%4];"
                 : "=r"(r[0]), "=r"(r[1]), "=r"(r[2]), "=r"(r[3]) : "r"(a));
}
__device__ __forceinline__ void ldsm4t(uint32_t* r, uint32_t a) {
    asm volatile("ldmatrix.sync.aligned.m8n8.x4.trans.shared.b16 {%0,%1,%2,%3},[%4];"
                 : "=r"(r[0]), "=r"(r[1]), "=r"(r[2]), "=r"(r[3]) : "r"(a));
}
__device__ __forceinline__ void mma_bf16(float* c, const uint32_t* a, const uint32_t* b) {
    asm volatile("mma.sync.aligned.m16n8k16.row.col.f32.bf16.bf16.f32 "
                 "{%0,%1,%2,%3},{%4,%5,%6,%7},{%8,%9},{%0,%1,%2,%3};"
                 : "+f"(c[0]), "+f"(c[1]), "+f"(c[2]), "+f"(c[3])
                 : "r"(a[0]), "r"(a[1]), "r"(a[2]), "r"(a[3]), "r"(b[0]), "r"(b[1]));
}

__global__ __launch_bounds__(256) void gemm_bf16x2_t(
    const __nv_bfloat16* __restrict__ Ahi, const __nv_bfloat16* __restrict__ Alo,
    const __nv_bfloat16* __restrict__ Bhi, const __nv_bfloat16* __restrict__ Blo,
    const float* __restrict__ bias, float* __restrict__ T)
{
    extern __shared__ __align__(16) char dsm[];

    const int tid = threadIdx.x;
    const int warp = tid >> 5, lane = tid & 31;
    const int wm = warp >> 2, wn = warp & 3;          // 2 x 4 warp grid
    const int m0 = blockIdx.y * 128, n0 = blockIdx.x * 128;

    float acc[4][4][4];
#pragma unroll
    for (int i = 0; i < 4; i++)
#pragma unroll
        for (int j = 0; j < 4; j++)
#pragma unroll
            for (int k = 0; k < 4; k++) acc[i][j][k] = 0.0f;

#define SAH(s) ((__nv_bfloat16*)(dsm + (s) * STAGE_BYTES))
#define SAL(s) ((__nv_bfloat16*)(dsm + (s) * STAGE_BYTES + A_BYTES))
#define SBH(s) ((__nv_bfloat16*)(dsm + (s) * STAGE_BYTES + 2 * A_BYTES))
#define SBL(s) ((__nv_bfloat16*)(dsm + (s) * STAGE_BYTES + 2 * A_BYTES + B_BYTES))

    // A: 128 rows x 4 16B-chunks (32 halves); B: 32 rows x 16 16B-chunks
#define GEMM_ISSUE(s, k0)                                                              \
    do {                                                                               \
        _Pragma("unroll")                                                              \
        for (int t = 0; t < 2; t++) {                                                  \
            const int id = tid + t * 256;                                              \
            const int arow = id >> 2, ac4 = id & 3;                                    \
            cp16((uint32_t)__cvta_generic_to_shared(SAH(s) + arow * APAD + ac4 * 8),   \
                 Ahi + (size_t)(m0 + arow) * 1024 + (k0) + ac4 * 8);                   \
            cp16((uint32_t)__cvta_generic_to_shared(SAL(s) + arow * APAD + ac4 * 8),   \
                 Alo + (size_t)(m0 + arow) * 1024 + (k0) + ac4 * 8);                   \
            const int brow = id >> 4, bc = id & 15;                                    \
            cp16((uint32_t)__cvta_generic_to_shared(SBH(s) + brow * BPAD + bc * 8),    \
                 Bhi + (size_t)((k0) + brow) * 1024 + n0 + bc * 8);                    \
            cp16((uint32_t)__cvta_generic_to_shared(SBL(s) + brow * BPAD + bc * 8),    \
                 Blo + (size_t)((k0) + brow) * 1024 + n0 + bc * 8);                    \
        }                                                                              \
        cp_commit();                                                                   \
    } while (0)

    GEMM_ISSUE(0, 0);
    GEMM_ISSUE(1, 32);

    const int ar = lane & 15, ac8 = (lane >> 4) * 8;    // ldmatrix lane addressing

    for (int it = 0; it < 32; it++) {
        if (it == 31) cp_wait0(); else cp_wait1();
        __syncthreads();

        const int s = it % 3;
#pragma unroll
        for (int kk = 0; kk < 32; kk += 16) {
            uint32_t ah[4][4], al[4][4], bh[4][2], bl[4][2];
#pragma unroll
            for (int mb = 0; mb < 4; mb++) {
                const int row = wm * 64 + mb * 16 + ar;
                ldsm4(ah[mb], (uint32_t)__cvta_generic_to_shared(SAH(s) + row * APAD + kk + ac8));
                ldsm4(al[mb], (uint32_t)__cvta_generic_to_shared(SAL(s) + row * APAD + kk + ac8));
            }
#pragma unroll
            for (int nb2 = 0; nb2 < 2; nb2++) {
                uint32_t r[4];
                const int col = wn * 32 + nb2 * 16 + ac8;
                ldsm4t(r, (uint32_t)__cvta_generic_to_shared(SBH(s) + (kk + ar) * BPAD + col));
                bh[nb2 * 2][0] = r[0]; bh[nb2 * 2][1] = r[1];
                bh[nb2 * 2 + 1][0] = r[2]; bh[nb2 * 2 + 1][1] = r[3];
                ldsm4t(r, (uint32_t)__cvta_generic_to_shared(SBL(s) + (kk + ar) * BPAD + col));
                bl[nb2 * 2][0] = r[0]; bl[nb2 * 2][1] = r[1];
                bl[nb2 * 2 + 1][0] = r[2]; bl[nb2 * 2 + 1][1] = r[3];
            }
            // Product-outermost: 16 independent mmas between same-acc reuse,
            // so the accumulator RAW (mma latency) is fully hidden.
#pragma unroll
            for (int mb = 0; mb < 4; mb++)
#pragma unroll
                for (int nb = 0; nb < 4; nb++)
                    mma_bf16(acc[mb][nb], ah[mb], bh[nb]);   // hi*hi
#pragma unroll
            for (int mb = 0; mb < 4; mb++)
#pragma unroll
                for (int nb = 0; nb < 4; nb++)
                    mma_bf16(acc[mb][nb], ah[mb], bl[nb]);   // hi*lo
#pragma unroll
            for (int mb = 0; mb < 4; mb++)
#pragma unroll
                for (int nb = 0; nb < 4; nb++)
                    mma_bf16(acc[mb][nb], al[mb], bh[nb]);   // lo*hi
        }
        if (it + 2 < 32) GEMM_ISSUE((it + 2) % 3, (it + 2) * 32);
    }

    // ---- Fused transposed epilogue: write T[b, c, l] (coalesced along l) ----
    float* sT = (float*)dsm;                 // 64 * 132 * 4 = 33792 B (fits)
    const int g = lane >> 2, t2 = (lane & 3) * 2;
    const int l0 = m0 & 2047;
    const int bq = m0 >> 11;

#pragma unroll
    for (int p = 0; p < 2; p++) {
        __syncthreads();
        if ((wn >> 1) == p) {
            const int chalf = (wn & 1) * 32;
#pragma unroll
            for (int mb = 0; mb < 4; mb++) {
                const int row = wm * 64 + mb * 16 + g;
#pragma unroll
                for (int nb = 0; nb < 4; nb++) {
                    const int cl = chalf + nb * 8 + t2;
                    const int cgl = n0 + p * 64 + cl;
                    const float b0 = bias[cgl], b1 = bias[cgl + 1];
                    sT[cl * 132 + row]           = acc[mb][nb][0] + b0;
                    sT[(cl + 1) * 132 + row]     = acc[mb][nb][1] + b1;
                    sT[cl * 132 + row + 8]       = acc[mb][nb][2] + b0;
                    sT[(cl + 1) * 132 + row + 8] = acc[mb][nb][3] + b1;
                }
            }
        }
        __syncthreads();
        const size_t cb = (size_t)bq * 1024 + n0 + p * 64;
#pragma unroll
        for (int i = tid; i < 2048; i += 256) {     // 64 c x 32 float4
            const int c = i >> 5, m4 = (i & 31) << 2;
            float4 v = *(float4*)&sT[c * 132 + m4];
            *(float4*)&T[((cb + c) << 11) + l0 + m4] = v;
        }
    }
}

// ---------------------------------------------------------------------------
// Small GEMM, coalesced: Y[64,1024] = X[64,1024] @ W + bias.
// Row r of X maps to X + (r/8)*b_stride + (r%8)*1024.
// ---------------------------------------------------------------------------
__global__ __launch_bounds__(256) void rowgemm64(
    const float* __restrict__ X, const float* __restrict__ W,
    const float* __restrict__ bias, float* __restrict__ Y, size_t b_stride)
{
    __shared__ float Xs[64][128];     // 32 KB
    __shared__ float Ws[16][129];

    const int tid = threadIdx.x;
    const int n0 = blockIdx.x * 16;
    const int n = tid & 15, rg = tid >> 4;   // 16 row-groups x 4 rows

    float a0 = 0.f, a1 = 0.f, a2 = 0.f, a3 = 0.f;

    for (int kt = 0; kt < 8; kt++) {
#pragma unroll
        for (int j = 0; j < 8; j++) {                 // X tile: 2048 float4
            const int i = tid + j * 256;
            const int row = i >> 5, c4 = (i & 31) << 2;
            const float* xr = X + (size_t)(row >> 3) * b_stride + (size_t)(row & 7) * 1024;
            *(float4*)&Xs[row][c4] = *(const float4*)(xr + kt * 128 + c4);
        }
#pragma unroll
        for (int j = 0; j < 8; j++) {                 // W tile: 128k x 16n -> Ws[n][k]
            const int i = tid + j * 256;
            const int k = i >> 4, nn = i & 15;
            Ws[nn][k] = W[(size_t)(kt * 128 + k) * 1024 + n0 + nn];
        }
        __syncthreads();
#pragma unroll 4
        for (int k = 0; k < 128; k++) {
            const float w = Ws[n][k];
            a0 += Xs[rg * 4 + 0][k] * w;
            a1 += Xs[rg * 4 + 1][k] * w;
            a2 += Xs[rg * 4 + 2][k] * w;
            a3 += Xs[rg * 4 + 3][k] * w;
        }
        __syncthreads();
    }
    const float bb = bias[n0 + n];
    Y[(size_t)(rg * 4 + 0) * 1024 + n0 + n] = a0 + bb;
    Y[(size_t)(rg * 4 + 1) * 1024 + n0 + n] = a1 + bb;
    Y[(size_t)(rg * 4 + 2) * 1024 + n0 + n] = a2 + bb;
    Y[(size_t)(rg * 4 + 3) * 1024 + n0 + n] = a3 + bb;
}

// ---------------------------------------------------------------------------
// Batched 2D transpose: out[b, j, i] = in[b, i, j], i<R, j<C (R,C mult of 32)
// ---------------------------------------------------------------------------
__global__ void transpose_bRC(const float* __restrict__ in, float* __restrict__ out,
                              int R, int C)
{
    __shared__ float tile[32][33];
    const int bz = blockIdx.z;
    const float* ip = in + (size_t)bz * R * C;
    float* op = out + (size_t)bz * R * C;
    const int j0 = blockIdx.x * 32;
    const int i0 = blockIdx.y * 32;
    const int tx = threadIdx.x, ty = threadIdx.y;
#pragma unroll
    for (int k = 0; k < 4; k++)
        tile[ty + k * 8][tx] = ip[(size_t)(i0 + ty + k * 8) * C + (j0 + tx)];
    __syncthreads();
#pragma unroll
    for (int k = 0; k < 4; k++)
        op[(size_t)(j0 + ty + k * 8) * R + (i0 + tx)] = tile[tx][ty + k * 8];
}

// ---------------------------------------------------------------------------
// FFT twiddle table: g_tw[e] = (cos, sin)(2 pi e / 2048), e < 1024
// ---------------------------------------------------------------------------
__global__ void fill_tw(float2* tw)
{
    const int i = blockIdx.x * 256 + threadIdx.x;
    if (i < 1024) {
        float s, c;
        sincosf(6.28318530717958647692f * (float)i / 2048.0f, &s, &c);
        tw[i] = make_float2(c, s);
    }
}

// ---------------------------------------------------------------------------
// Register-resident mixed-radix FFT, N=2048 = 16 * 16 * 8, 128 threads.
// Stockham: y_m = DFT_R(x)_m * w2048^{m*p*s}, outputs at q + R*s*p + m*s.
// Twiddle: w2048^e with tw[e<1024]; e in [1024,2048) -> negate.
// ---------------------------------------------------------------------------
#define PD(i) ((i) + ((i) >> 4))          // padded smem index (float2 units)
#define FFT_SSZ 2176                       // PD(2047)+1 = 2174 -> round up

__device__ __forceinline__ float2 cmul(float2 a, float2 b) {
    return make_float2(a.x * b.x - a.y * b.y, a.x * b.y + a.y * b.x);
}
__device__ __forceinline__ float2 twget(const float2* tw, int e, float sign) {
    float2 t = __ldg(&tw[e & 1023]);
    const float fl = (e & 1024) ? -1.0f : 1.0f;
    return make_float2(fl * t.x, fl * sign * t.y);
}
__device__ __forceinline__ void dft4(float2& x0, float2& x1, float2& x2, float2& x3,
                                     float sign) {
    const float apcx = x0.x + x2.x, apcy = x0.y + x2.y;
    const float amcx = x0.x - x2.x, amcy = x0.y - x2.y;
    const float bpdx = x1.x + x3.x, bpdy = x1.y + x3.y;
    const float bmdx = x1.x - x3.x, bmdy = x1.y - x3.y;
    x0 = make_float2(apcx + bpdx, apcy + bpdy);
    x1 = make_float2(amcx - sign * bmdy, amcy + sign * bmdx);
    x2 = make_float2(apcx - bpdx, apcy - bpdy);
    x3 = make_float2(amcx + sign * bmdy, amcy - sign * bmdx);
}
// In-place DFT16; output X_{(s>>2)+4*(s&3)} lands in slot s.
__device__ __forceinline__ void dft16(float2* x, const float2* tw, float sign) {
#pragma unroll
    for (int j1 = 0; j1 < 4; j1++)
        dft4(x[j1], x[j1 + 4], x[j1 + 8], x[j1 + 12], sign);
#pragma unroll
    for (int j1 = 1; j1 < 4; j1++)
#pragma unroll
        for (int k2 = 1; k2 < 4; k2++)
            x[j1 + 4 * k2] = cmul(x[j1 + 4 * k2], twget(tw, 128 * j1 * k2, sign));
#pragma unroll
    for (int k2 = 0; k2 < 4; k2++)
        dft4(x[4 * k2], x[1 + 4 * k2], x[2 + 4 * k2], x[3 + 4 * k2], sign);
}
// In-place DFT8, natural-order output in x[0..7].
__device__ __forceinline__ void dft8(float2* x, float sign) {
    const float s2 = 0.70710678118654752440f;
    float2 e[4], o[4];
#pragma unroll
    for (int j = 0; j < 4; j++) {
        e[j] = make_float2(x[j].x + x[j + 4].x, x[j].y + x[j + 4].y);
        o[j] = make_float2(x[j].x - x[j + 4].x, x[j].y - x[j + 4].y);
    }
    o[1] = cmul(o[1], make_float2(s2, sign * s2));
    o[2] = make_float2(-sign * o[2].y, sign * o[2].x);
    o[3] = cmul(o[3], make_float2(-s2, sign * s2));
    dft4(e[0], e[1], e[2], e[3], sign);
    dft4(o[0], o[1], o[2], o[3], sign);
#pragma unroll
    for (int k = 0; k < 4; k++) { x[2 * k] = e[k]; x[2 * k + 1] = o[k]; }
}

// x[m] = in[tid + 128m] on entry. Result (natural order) lands in Sa[PD(n)].
__device__ __forceinline__ void fft2048_reg(float2* x, float2* Sa, float2* Sb,
                                            const float2* tw, int tid, float sign)
{
    // Stage A: radix-16, s=1, p=tid, q=0
    dft16(x, tw, sign);
#pragma unroll
    for (int s = 0; s < 16; s++) {
        const int m = (s >> 2) | ((s & 3) << 2);
        Sa[PD(16 * tid + m)] = cmul(x[s], twget(tw, m * tid, sign));
    }
    __syncthreads();
    // Stage B: radix-16, s=16, q=tid&15, p=tid>>4
    {
        const int q = tid & 15, p = tid >> 4;
#pragma unroll
        for (int m = 0; m < 16; m++) x[m] = Sa[PD(q + 16 * p + 128 * m)];
        dft16(x, tw, sign);
        const int e = 16 * p;
        const int ob = q + 256 * p;
#pragma unroll
        for (int s = 0; s < 16; s++) {
            const int m = (s >> 2) | ((s & 3) << 2);
            Sb[PD(ob + 16 * m)] = cmul(x[s], twget(tw, m * e, sign));
        }
    }
    __syncthreads();
    // Stage C: radix-8, s=256, p=0 (twiddle-free), 2 butterflies/thread
#pragma unroll
    for (int h = 0; h < 2; h++) {
        const int q = tid + 128 * h;
        float2 y[8];
#pragma unroll
        for (int m = 0; m < 8; m++) y[m] = Sb[PD(q + 256 * m)];
        dft8(y, sign);
#pragma unroll
        for (int m = 0; m < 8; m++) Sa[PD(q + 256 * m)] = y[m];
    }
    __syncthreads();
}

// ---------------------------------------------------------------------------
// Per-(b,c) kernel: packed register-FFT correlation -> corr, then parallel
// top-22 (single barrier per round) + softmax + mod-8 V aggregation.
// ---------------------------------------------------------------------------
__global__ __launch_bounds__(128) void fft_corr_topk(
    const float* __restrict__ Qt, const float* __restrict__ Kt,
    const float* __restrict__ Vs, const float2* __restrict__ twg,
    float* __restrict__ corrS, float* __restrict__ Rsmall)
{
    __shared__ float2 S1[FFT_SSZ];
    __shared__ float2 S2[FFT_SSZ];
    __shared__ float topv[TOPK];
    __shared__ int   topd[TOPK];
    __shared__ float wts[TOPK];
    __shared__ float vsh[8];
    __shared__ float wv[2][4];    // parity double-buffered per round
    __shared__ int   wi[2][4];

    const int tid = threadIdx.x;
    const int lane = tid & 31, warp = tid >> 5;
    const int bidx = blockIdx.x;              // b*1024 + c
    const int b = bidx >> 10;
    const int c = bidx & 1023;

    const float* qp = Qt + (size_t)bidx * 2048;
    const float* kp = Kt + (size_t)bidx * 2048;

    float2 x[16];
    // Forward FFT of z = q + i*k (load gmem -> regs), result -> S1
#pragma unroll
    for (int m = 0; m < 16; m++) {
        const int n = tid + (m << 7);
        x[m] = make_float2(qp[n], kp[n]);
    }
    fft2048_reg(x, S1, S2, twg, tid, -1.0f);

    // P[f] = Q[f]*conj(K[f]) = 0.25i * (a + conj(b)) * (conj(a) - b)  -> S2
#pragma unroll
    for (int m = 0; m < 16; m++) {
        const int f = tid + (m << 7);
        float2 a  = S1[PD(f)];
        float2 bz = S1[PD((2048 - f) & 2047)];
        float ux = a.x + bz.x, uy = a.y - bz.y;
        float vx = a.x - bz.x, vy = -a.y - bz.y;
        float pr = ux * vx - uy * vy;
        float pi = ux * vy + uy * vx;
        S2[PD(f)] = make_float2(-0.25f * pi, 0.25f * pr);
    }
    __syncthreads();

    // Inverse FFT of P (load S2 -> regs), result -> S1
#pragma unroll
    for (int m = 0; m < 16; m++) x[m] = S2[PD(tid + (m << 7))];
    fft2048_reg(x, S1, S2, twg, tid, +1.0f);

    // ---- corr to global + register-resident values for top-k ----
    const float invN = 1.0f / 2048.0f;
    float* cg = corrS + (size_t)bidx * 2048;
    float vals[16];
#pragma unroll
    for (int m = 0; m < 16; m++) {
        const int n = tid + (m << 7);
        const float v = S1[PD(n)].x * invN;
        vals[m] = v;
        cg[n] = v;
    }

    // local argmax (ascending m scan => lowest index kept on ties)
    float lmax = vals[0]; int lidx = tid;
#pragma unroll
    for (int m = 1; m < 16; m++) {
        const int ii = tid + (m << 7);
        if (vals[m] > lmax) { lmax = vals[m]; lidx = ii; }
    }

    // ---- top-22: one barrier per round; all threads redundantly pick winner --
    for (int r = 0; r < TOPK; r++) {
        const int pb = r & 1;
        float bvv = lmax; int bii = lidx;
#pragma unroll
        for (int off = 16; off > 0; off >>= 1) {
            const float ov = __shfl_down_sync(0xffffffffu, bvv, off);
            const int   oi = __shfl_down_sync(0xffffffffu, bii, off);
            if (ov > bvv || (ov == bvv && oi < bii)) { bvv = ov; bii = oi; }
        }
        if (lane == 0) { wv[pb][warp] = bvv; wi[pb][warp] = bii; }
        __syncthreads();
        // every thread computes the block winner (identical result)
        float v2 = wv[pb][0]; int i2 = wi[pb][0];
#pragma unroll
        for (int w = 1; w < 4; w++) {
            const float ww = wv[pb][w]; const int qq = wi[pb][w];
            if (ww > v2 || (ww == v2 && qq < i2)) { v2 = ww; i2 = qq; }
        }
        if (tid == 0) { topv[r] = v2; topd[r] = i2; }
        if ((i2 & 127) == tid) {
            const int jj = i2 >> 7;
#pragma unroll
            for (int m = 0; m < 16; m++) if (m == jj) vals[m] = -1e30f;
            lmax = vals[0]; lidx = tid;
#pragma unroll
            for (int m = 1; m < 16; m++) {
                const int ii = tid + (m << 7);
                if (vals[m] > lmax) { lmax = vals[m]; lidx = ii; }
            }
        }
    }
    __syncthreads();   // topv/topd visible to warp 0

    // ---- softmax over top-22 + mod-8 aggregation (warp 0) ----
    if (tid < 32) {
        float e = 0.0f;
        const float mx = topv[0];
        if (lane < TOPK) { e = expf(topv[lane] - mx); wts[lane] = e; }
        float ssum = e;
#pragma unroll
        for (int off = 16; off > 0; off >>= 1)
            ssum += __shfl_down_sync(0xffffffffu, ssum, off);
        ssum = __shfl_sync(0xffffffffu, ssum, 0);
        const float inv = 1.0f / ssum;
        if (lane < 8) vsh[lane] = Vs[(size_t)(((b << 3) + lane) << 10) + c];
        __syncwarp();
        if (lane < 8) {
            float acc = 0.0f;
#pragma unroll
            for (int i = 0; i < TOPK; i++)
                acc += wts[i] * vsh[(lane + topd[i]) & 7];
            Rsmall[(size_t)(((b << 3) + lane) << 10) + c] = acc * inv;
        }
    }
}

// ---------------------------------------------------------------------------
// Broadcast: out[b,l,:] = Tout[b*8 + (l%8), :]
// ---------------------------------------------------------------------------
__global__ void broadcast_out(const float* __restrict__ Tout, float* __restrict__ out)
{
    const size_t idx = (size_t)blockIdx.x * 256 + threadIdx.x;  // < ELEMS
    const int cc = (int)(idx & 1023);
    const int l  = (int)((idx >> 10) & 2047);
    const int bb = (int)(idx >> 21);
    out[idx] = Tout[(size_t)(((bb << 3) + (l & 7)) << 10) + cc];
}

// ---------------------------------------------------------------------------
extern "C" void kernel_launch(void* const* d_in, const int* in_sizes, int n_in,
                              void* d_out, int out_size)
{
    (void)in_sizes; (void)n_in; (void)out_size;
    const float* queries = (const float*)d_in[0];
    const float* keys    = (const float*)d_in[1];
    const float* values  = (const float*)d_in[2];
    const float* Wq = (const float*)d_in[3];
    const float* bq = (const float*)d_in[4];
    const float* Wk = (const float*)d_in[5];
    const float* bk = (const float*)d_in[6];
    const float* Wv = (const float*)d_in[7];
    const float* bv = (const float*)d_in[8];
    const float* Wo = (const float*)d_in[9];
    const float* bo = (const float*)d_in[10];
    float* out = (float*)d_out;

    float *Qt, *Kt, *corrS, *Vs, *Rs, *To;
    __nv_bfloat16 *Xhi, *Xlo, *Whi, *Wlo;
    float2* twp;
    cudaGetSymbolAddress((void**)&Qt, g_Qt);
    cudaGetSymbolAddress((void**)&Kt, g_Kt);
    cudaGetSymbolAddress((void**)&corrS, g_corr);
    cudaGetSymbolAddress((void**)&Vs, g_Vs);
    cudaGetSymbolAddress((void**)&Rs, g_Rs);
    cudaGetSymbolAddress((void**)&To, g_To);
    cudaGetSymbolAddress((void**)&Xhi, g_Xhi);
    cudaGetSymbolAddress((void**)&Xlo, g_Xlo);
    cudaGetSymbolAddress((void**)&Whi, g_Whi);
    cudaGetSymbolAddress((void**)&Wlo, g_Wlo);
    cudaGetSymbolAddress((void**)&twp, g_tw);

    static int attr_done = 0;
    if (!attr_done) {
        cudaFuncSetAttribute(gemm_bf16x2_t,
                             cudaFuncAttributeMaxDynamicSharedMemorySize, GEMM_DSMEM);
        attr_done = 1;
    }

    fill_tw<<<4, 256>>>(twp);

    dim3 gemmGrid(1024 / 128, (BATCH * SEQ) / 128);  // (8, 128)

    // Q projection on tensor cores (split-bf16, 3 products), writes Qt directly
    split_bf16<<<ELEMS / 1024, 256>>>(queries, Xhi, Xlo);
    split_bf16<<<(DIM * DIM) / 1024, 256>>>(Wq, Whi, Wlo);
    gemm_bf16x2_t<<<gemmGrid, 256, GEMM_DSMEM>>>(Xhi, Xlo, Whi, Wlo, bq, Qt);

    // K projection, writes Kt directly
    split_bf16<<<ELEMS / 1024, 256>>>(keys, Xhi, Xlo);
    split_bf16<<<(DIM * DIM) / 1024, 256>>>(Wk, Whi, Wlo);
    gemm_bf16x2_t<<<gemmGrid, 256, GEMM_DSMEM>>>(Xhi, Xlo, Whi, Wlo, bk, Kt);

    // V projection: only rows l = 0..7 per batch matter (mod-8 quirk)
    rowgemm64<<<64, 256>>>(values, Wv, bv, Vs, (size_t)SEQ * DIM);

    // FFT correlation + top-k + mod-8 aggregation
    fft_corr_topk<<<BATCH * DIM, 128>>>(Qt, Kt, Vs, twp, corrS, Rs);

    // corr [B,C,L] -> second output half [B,L,C]
    transpose_bRC<<<dim3(2048 / 32, 1024 / 32, BATCH), dim3(32, 8)>>>(corrS, out + (size_t)ELEMS, 1024, 2048);

    // out = result @ Wo + bo  (result rows periodic: 64 distinct rows)
    rowgemm64<<<64, 256>>>(Rs, Wo, bo, To, (size_t)8 * DIM);
    broadcast_out<<<ELEMS / 256, 256>>>(To, out);
}